// round 3
// baseline (speedup 1.0000x reference)
#include <cuda_runtime.h>
#include <cstdint>
#include <cstddef>

#define DECAY 0.9f

#define B_ 2
#define S_ 2048
#define V_ 32000
#define E_ 1024
#define H_ 2048
#define M_ (B_*S_)   // 4096 rows

// Scratch (allocation-free rule: device globals, zero-init .bss)
__device__ float g_buf1[(size_t)M_ * H_];    // 32 MB: cur1 / spikes1 (in-place)
__device__ float g_buf2[(size_t)M_ * E_];    // 16 MB: cur2 / spikes2 (in-place)
__device__ float g_embA[(size_t)M_ * E_];    // 16 MB: gathered+rounded embeddings
__device__ float g_encWr[(size_t)E_ * H_];   //  8 MB: tf32-rounded enc_W
__device__ float g_decWr[(size_t)H_ * E_];   //  8 MB: tf32-rounded dec_W
__device__ float g_outWr[(size_t)E_ * V_];   // 131 MB: tf32-rounded out_W
__device__ int   g_ids_is64;

// ---------------------------------------------------------------------------
// helpers
// ---------------------------------------------------------------------------
__device__ __forceinline__ float tf32r(float x) {
    unsigned u; asm("cvt.rna.tf32.f32 %0, %1;" : "=r"(u) : "f"(x));
    return __uint_as_float(u);
}
__device__ __forceinline__ float fast_ex2(float x) {
    float y; asm("ex2.approx.f32 %0, %1;" : "=f"(y) : "f"(x)); return y;
}
__device__ __forceinline__ float fast_rcp(float x) {
    float y; asm("rcp.approx.f32 %0, %1;" : "=f"(y) : "f"(x)); return y;
}
__device__ __forceinline__ void mma8(float* c, const unsigned* a, const unsigned* b) {
    asm volatile(
        "mma.sync.aligned.m16n8k8.row.col.f32.tf32.tf32.f32 "
        "{%0,%1,%2,%3}, {%4,%5,%6,%7}, {%8,%9}, {%0,%1,%2,%3};\n"
        : "+f"(c[0]), "+f"(c[1]), "+f"(c[2]), "+f"(c[3])
        : "r"(a[0]), "r"(a[1]), "r"(a[2]), "r"(a[3]), "r"(b[0]), "r"(b[1]));
}
__device__ __forceinline__ uint32_t smem_u32(const void* p) {
    uint32_t a;
    asm("{ .reg .u64 t; cvta.to.shared.u64 t, %1; cvt.u32.u64 %0, t; }" : "=r"(a) : "l"(p));
    return a;
}
__device__ __forceinline__ void cp16(uint32_t s, const void* g) {
    asm volatile("cp.async.cg.shared.global [%0], [%1], 16;" :: "r"(s), "l"(g) : "memory");
}
__device__ __forceinline__ void cp_commit() {
    asm volatile("cp.async.commit_group;" ::: "memory");
}
template<int N>
__device__ __forceinline__ void cp_wait() {
    asm volatile("cp.async.wait_group %0;" :: "n"(N) : "memory");
}

// ---------------------------------------------------------------------------
// dtype sniffer for input_ids (int32 vs int64)
// ---------------------------------------------------------------------------
__global__ void sniff_ids(const int* __restrict__ ids32) {
    if (threadIdx.x == 0 && blockIdx.x == 0) {
        int zeros = 0;
        for (int i = 1; i < 255; i += 2) zeros += (ids32[i] == 0);
        g_ids_is64 = (zeros > 64) ? 1 : 0;
    }
}

// ---------------------------------------------------------------------------
// pre-round passes (everything entering an MMA is tf32-rounded ONCE here,
// so the GEMM mainloop is pure cp.async + LDS + HMMA, no cvt)
// ---------------------------------------------------------------------------
__global__ void round_arr(const float* __restrict__ src, float* __restrict__ dst, int n4) {
    int i = blockIdx.x * blockDim.x + threadIdx.x;
    if (i < n4) {
        float4 v = ((const float4*)src)[i];
        v.x = tf32r(v.x); v.y = tf32r(v.y); v.z = tf32r(v.z); v.w = tf32r(v.w);
        ((float4*)dst)[i] = v;
    }
}

__global__ void gather_round(const float* __restrict__ emb, const void* __restrict__ idsv,
                             float* __restrict__ dst) {
    const int row = blockIdx.x;
    long long id = g_ids_is64 ? ((const long long*)idsv)[row]
                              : (long long)((const int*)idsv)[row];
    const float4* s = (const float4*)(emb + (size_t)id * E_);
    float4* d = (float4*)(dst + (size_t)row * E_);
    for (int c = threadIdx.x; c < E_ / 4; c += blockDim.x) {
        float4 v = s[c];
        v.x = tf32r(v.x); v.y = tf32r(v.y); v.z = tf32r(v.z); v.w = tf32r(v.w);
        d[c] = v;
    }
}

// ---------------------------------------------------------------------------
// Pipelined tf32 mma.sync GEMM:  C[M,N] = (A@W + bias) * rowscale
//   A: MxK row-major, tf32-pre-rounded. W: KxN row-major, tf32-pre-rounded.
//   Block tile 128x256x32, 4-stage cp.async pipeline, 256 threads,
//   8 warps as 2m x 4n, warp tile 64x64 (m16n8k8 frags).
//   Requires M%128==0, N%256==0, K%32==0.
// ---------------------------------------------------------------------------
#define PBM 128
#define PBN 256
#define PBK 32
#define STAGES 4
#define AS_P 36                      // A smem pitch (floats): conflict-free frags
#define BS_P 264                     // B smem pitch (floats): conflict-free frags
#define ASZ (PBM * AS_P)             // 4608 floats
#define BSZ (PBK * BS_P)             // 8448 floats
#define STG_F (ASZ + BSZ)            // 13056 floats / stage
#define SMEM_BYTES (STAGES * STG_F * 4)   // 208,896 B

template<bool SCALE>
__global__ void __launch_bounds__(256, 1)
gemm_pipe(const float* __restrict__ A, const float* __restrict__ W,
          const float* __restrict__ bias, const float* __restrict__ gains,
          float strength, float* __restrict__ C, int M, int N, int K)
{
    extern __shared__ __align__(16) float sm[];
    const uint32_t sbase = smem_u32(sm);

    const int tid = threadIdx.x;
    const int bm0 = blockIdx.x * PBM;
    const int bn0 = blockIdx.y * PBN;

    // ---- copy mapping ----
    // A: 128 rows x 8 chunks(16B); thread -> row tid>>1, chunks (tid&1)*4 + j (j<4)
    const int arow   = tid >> 1;
    const int achunk = (tid & 1) * 4;
    const float* ag  = A + (size_t)(bm0 + arow) * K;
    // B: 32 rows x 64 chunks; thread -> row tid>>3, chunks (tid&7) + 8j (j<8)
    const int brow = tid >> 3;
    const int bc   = tid & 7;
    const float* wg = W + (size_t)brow * N + bn0;

    const int niter = K / PBK;

    // ---- issue one stage of cp.async ----
    auto issue = [&](int stage, int k0) {
        const uint32_t sa = sbase + stage * (STG_F * 4);
        #pragma unroll
        for (int j = 0; j < 4; j++)
            cp16(sa + arow * (AS_P * 4) + (achunk + j) * 16,
                 ag + k0 + (achunk + j) * 4);
        const uint32_t sb = sa + ASZ * 4;
        const float* wk = wg + (size_t)k0 * N;
        #pragma unroll
        for (int j = 0; j < 8; j++)
            cp16(sb + brow * (BS_P * 4) + (bc + 8 * j) * 16,
                 wk + (bc + 8 * j) * 4);
    };

    // ---- mma thread mapping: 8 warps 2m x 4n, warp tile 64x64 ----
    const int lane = tid & 31;
    const int wid  = tid >> 5;
    const int wm   = (wid & 1) * 64;     // warp m origin (0/64)
    const int wn   = (wid >> 1) * 64;    // warp n origin (0/64/128/192)
    const int ar   = lane >> 2;          // 0..7
    const int ac   = lane & 3;           // 0..3

    float acc[4][8][4];
    #pragma unroll
    for (int mi = 0; mi < 4; mi++)
        #pragma unroll
        for (int ni = 0; ni < 8; ni++)
            #pragma unroll
            for (int j = 0; j < 4; j++) acc[mi][ni][j] = 0.f;

    // ---- prologue: fill STAGES-1 stages ----
    #pragma unroll
    for (int s = 0; s < STAGES - 1; s++) {
        if (s < niter) issue(s, s * PBK);
        cp_commit();
    }

    // ---- mainloop ----
    for (int kt = 0; kt < niter; kt++) {
        cp_wait<STAGES - 2>();
        __syncthreads();

        const int nk = kt + STAGES - 1;
        if (nk < niter) issue(nk % STAGES, nk * PBK);
        cp_commit();

        const float* as = sm + (kt % STAGES) * STG_F;
        const float* bs = as + ASZ;

        #pragma unroll
        for (int ks = 0; ks < PBK; ks += 8) {
            unsigned a[4][4], b[8][2];
            #pragma unroll
            for (int mi = 0; mi < 4; mi++) {
                const float* ap = as + (wm + mi * 16 + ar) * AS_P + ks + ac;
                a[mi][0] = __float_as_uint(ap[0]);
                a[mi][1] = __float_as_uint(ap[8 * AS_P]);
                a[mi][2] = __float_as_uint(ap[4]);
                a[mi][3] = __float_as_uint(ap[8 * AS_P + 4]);
            }
            #pragma unroll
            for (int ni = 0; ni < 8; ni++) {
                const float* bp = bs + (ks + ac) * BS_P + wn + ni * 8 + ar;
                b[ni][0] = __float_as_uint(bp[0]);
                b[ni][1] = __float_as_uint(bp[4 * BS_P]);
            }
            #pragma unroll
            for (int mi = 0; mi < 4; mi++)
                #pragma unroll
                for (int ni = 0; ni < 8; ni++)
                    mma8(acc[mi][ni], a[mi], b[ni]);
        }
    }

    // ---- epilogue: bias + optional row scale ----
    #pragma unroll
    for (int mi = 0; mi < 4; mi++) {
        const int r0 = bm0 + wm + mi * 16 + ar;
        const int r1 = r0 + 8;
        float s0 = 1.f, s1 = 1.f;
        if (SCALE) {
            s0 = 1.f + strength * (gains[r0] - 1.f);
            s1 = 1.f + strength * (gains[r1] - 1.f);
        }
        #pragma unroll
        for (int ni = 0; ni < 8; ni++) {
            const int col = bn0 + wn + ni * 8 + ac * 2;
            const float b0 = bias[col], b1 = bias[col + 1];
            float2 o0, o1;
            o0.x = (acc[mi][ni][0] + b0) * s0;
            o0.y = (acc[mi][ni][1] + b1) * s0;
            o1.x = (acc[mi][ni][2] + b0) * s1;
            o1.y = (acc[mi][ni][3] + b1) * s1;
            *(float2*)&C[(size_t)r0 * N + col] = o0;
            *(float2*)&C[(size_t)r1 * N + col] = o1;
        }
    }
}

// ---------------------------------------------------------------------------
// GIF scan: per (b,d) channel, sequential over S (in place: cur -> spikes)
//   v' = 0.9 v + c ; s = sigmoid(4(v'-1)) ; v = v' - s
// Stores tf32-ROUNDED spikes (they feed the next GEMM; rounding here is
// exactly the rounding the GEMM would have applied to its A operand).
// ---------------------------------------------------------------------------
__global__ void gif_scan(float* __restrict__ buf, int D)
{
    const int t = blockIdx.x * blockDim.x + threadIdx.x;
    if (t >= B_ * D) return;
    const int b = t / D, d = t % D;
    float* p = buf + (size_t)b * S_ * D + d;

    const float KX = 4.0f * 1.4426950408889634f;  // 4*log2(e)
    float v = 0.f;
    #pragma unroll 1
    for (int s0 = 0; s0 < S_; s0 += 8) {
        float c[8];
        #pragma unroll
        for (int i = 0; i < 8; i++) c[i] = p[(size_t)(s0 + i) * D];
        #pragma unroll
        for (int i = 0; i < 8; i++) {
            v = fmaf(DECAY, v, c[i]);
            const float e  = fast_ex2(fmaf(-KX, v, KX));   // exp(-4(v-1))
            const float sp = fast_rcp(1.0f + e);
            p[(size_t)(s0 + i) * D] = tf32r(sp);
            v -= sp;
        }
    }
}

// ---------------------------------------------------------------------------
// launch
// ---------------------------------------------------------------------------
extern "C" void kernel_launch(void* const* d_in, const int* in_sizes, int n_in,
                              void* d_out, int out_size)
{
    const void*  ids   = d_in[0];
    const float* gains = (const float*)d_in[1];
    const float* emb   = (const float*)d_in[2];
    const float* encW  = (const float*)d_in[3];
    const float* encb  = (const float*)d_in[4];
    const float* decW  = (const float*)d_in[5];
    const float* decb  = (const float*)d_in[6];
    const float* outW  = (const float*)d_in[7];
    const float* outb  = (const float*)d_in[8];
    float* out = (float*)d_out;

    float *buf1, *buf2, *embA, *encWr, *decWr, *outWr;
    cudaGetSymbolAddress((void**)&buf1,  g_buf1);
    cudaGetSymbolAddress((void**)&buf2,  g_buf2);
    cudaGetSymbolAddress((void**)&embA,  g_embA);
    cudaGetSymbolAddress((void**)&encWr, g_encWr);
    cudaGetSymbolAddress((void**)&decWr, g_decWr);
    cudaGetSymbolAddress((void**)&outWr, g_outWr);

    cudaFuncSetAttribute(gemm_pipe<true>,  cudaFuncAttributeMaxDynamicSharedMemorySize, SMEM_BYTES);
    cudaFuncSetAttribute(gemm_pipe<false>, cudaFuncAttributeMaxDynamicSharedMemorySize, SMEM_BYTES);

    sniff_ids<<<1, 32>>>((const int*)ids);

    // pre-round all MMA operands (tf32, rna)
    gather_round<<<M_, 256>>>(emb, ids, embA);
    round_arr<<<(E_*H_/4 + 255)/256, 256>>>(encW, encWr, E_*H_/4);
    round_arr<<<(H_*E_/4 + 255)/256, 256>>>(decW, decWr, H_*E_/4);
    round_arr<<<(E_*V_/4 + 255)/256, 256>>>(outW, outWr, E_*V_/4);

    // enc: cur1 = (embA @ encW + encb) * (1+0.3*(g-1))   [4096 x 2048, K=1024]
    gemm_pipe<true><<<dim3(M_/PBM, H_/PBN), 256, SMEM_BYTES>>>(
        embA, encWr, encb, gains, 0.3f, buf1, M_, H_, E_);
    gif_scan<<<(B_*H_ + 127) / 128, 128>>>(buf1, H_);

    // dec: cur2 = (spikes1 @ decW + decb) * (1+0.2*(g-1)) [4096 x 1024, K=2048]
    gemm_pipe<true><<<dim3(M_/PBM, E_/PBN), 256, SMEM_BYTES>>>(
        buf1, decWr, decb, gains, 0.2f, buf2, M_, E_, H_);
    gif_scan<<<(B_*E_ + 127) / 128, 128>>>(buf2, E_);

    // out: logits = spikes2 @ outW + outb                 [4096 x 32000, K=1024]
    gemm_pipe<false><<<dim3(M_/PBM, V_/PBN), 256, SMEM_BYTES>>>(
        buf2, outWr, outb, nullptr, 0.f, out, M_, V_, E_);
}

// round 4
// speedup vs baseline: 1.0083x; 1.0083x over previous
#include <cuda_runtime.h>
#include <cuda_fp16.h>
#include <cstdint>
#include <cstddef>

#define DECAY 0.9f

#define B_ 2
#define S_ 2048
#define V_ 32000
#define E_ 1024
#define H_ 2048
#define M_ (B_*S_)   // 4096 rows

// Scratch (allocation-free rule: device globals)
__device__ float  g_buf1[(size_t)M_ * H_];    // 32 MB: cur1 (f32)
__device__ float  g_buf2[(size_t)M_ * E_];    // 16 MB: cur2 (f32)
__device__ __half g_s1h [(size_t)M_ * H_];    // 16 MB: spikes1 (fp16)
__device__ __half g_s2h [(size_t)M_ * E_];    //  8 MB: spikes2 (fp16)
__device__ __half g_embH[(size_t)M_ * E_];    //  8 MB: gathered embeddings (fp16)
__device__ __half g_encWt[(size_t)H_ * E_];   //  4 MB: enc_W^T  [H][E]
__device__ __half g_decWt[(size_t)E_ * H_];   //  4 MB: dec_W^T  [E][H]
__device__ __half g_outWt[(size_t)V_ * E_];   // 64 MB: out_W^T  [V][E]
__device__ int    g_ids_is64;

// ---------------------------------------------------------------------------
// helpers
// ---------------------------------------------------------------------------
__device__ __forceinline__ float fast_ex2(float x) {
    float y; asm("ex2.approx.f32 %0, %1;" : "=f"(y) : "f"(x)); return y;
}
__device__ __forceinline__ float fast_rcp(float x) {
    float y; asm("rcp.approx.f32 %0, %1;" : "=f"(y) : "f"(x)); return y;
}
__device__ __forceinline__ void mma16(float* c, const unsigned* a, const unsigned* b) {
    asm volatile(
        "mma.sync.aligned.m16n8k16.row.col.f32.f16.f16.f32 "
        "{%0,%1,%2,%3}, {%4,%5,%6,%7}, {%8,%9}, {%0,%1,%2,%3};\n"
        : "+f"(c[0]), "+f"(c[1]), "+f"(c[2]), "+f"(c[3])
        : "r"(a[0]), "r"(a[1]), "r"(a[2]), "r"(a[3]), "r"(b[0]), "r"(b[1]));
}
__device__ __forceinline__ uint32_t smem_u32(const void* p) {
    uint32_t a;
    asm("{ .reg .u64 t; cvta.to.shared.u64 t, %1; cvt.u32.u64 %0, t; }" : "=r"(a) : "l"(p));
    return a;
}
__device__ __forceinline__ void cp16(uint32_t s, const void* g) {
    asm volatile("cp.async.cg.shared.global [%0], [%1], 16;" :: "r"(s), "l"(g) : "memory");
}
__device__ __forceinline__ void cp_commit() {
    asm volatile("cp.async.commit_group;" ::: "memory");
}
template<int N>
__device__ __forceinline__ void cp_wait() {
    asm volatile("cp.async.wait_group %0;" :: "n"(N) : "memory");
}

// ---------------------------------------------------------------------------
// dtype sniffer for input_ids (int32 vs int64)
// ---------------------------------------------------------------------------
__global__ void sniff_ids(const int* __restrict__ ids32) {
    if (threadIdx.x == 0 && blockIdx.x == 0) {
        int zeros = 0;
        for (int i = 1; i < 255; i += 2) zeros += (ids32[i] == 0);
        g_ids_is64 = (zeros > 64) ? 1 : 0;
    }
}

// ---------------------------------------------------------------------------
// weight transpose + fp32->fp16:  W[K][N] -> Wt[N][K]
// ---------------------------------------------------------------------------
__global__ void conv_transpose(const float* __restrict__ W, __half* __restrict__ Wt,
                               int K, int N)
{
    __shared__ float t[32][33];
    const int k0 = blockIdx.y * 32, n0 = blockIdx.x * 32;
    const int tx = threadIdx.x, ty = threadIdx.y;   // 32 x 8
    #pragma unroll
    for (int i = 0; i < 32; i += 8)
        t[ty + i][tx] = W[(size_t)(k0 + ty + i) * N + n0 + tx];
    __syncthreads();
    #pragma unroll
    for (int i = 0; i < 32; i += 8)
        Wt[(size_t)(n0 + ty + i) * K + k0 + tx] = __float2half_rn(t[tx][ty + i]);
}

// ---------------------------------------------------------------------------
// embedding gather -> fp16
// ---------------------------------------------------------------------------
__global__ void gather_h(const float* __restrict__ emb, const void* __restrict__ idsv,
                         __half* __restrict__ dst)
{
    const int row = blockIdx.x;
    long long id = g_ids_is64 ? ((const long long*)idsv)[row]
                              : (long long)((const int*)idsv)[row];
    const float4* s = (const float4*)(emb + (size_t)id * E_);
    __half2* d = (__half2*)(dst + (size_t)row * E_);
    const int c = threadIdx.x;            // 256 threads, E/4 = 256 float4
    float4 v = s[c];
    d[2*c]   = __floats2half2_rn(v.x, v.y);
    d[2*c+1] = __floats2half2_rn(v.z, v.w);
}

// ---------------------------------------------------------------------------
// fp16 NT GEMM:  C[M,N](f32) = (A[M,K](h) @ Wt[N,K](h)^T + bias) * rowscale
// Block 128x256x32, 5-stage cp.async, 8 warps (2m x 4n), warp 64x64,
// mma.m16n8k16. SMEM rows: pitch 40 halfs (80B) => conflict-free .b32 frags.
// Requires M%128==0, N%256==0, K%32==0.
// ---------------------------------------------------------------------------
#define PBM 128
#define PBN 256
#define PBK 32
#define STAGES 5
#define ROW_B 80                              // bytes per smem row (40 halfs)
#define A_BYTES (PBM * ROW_B)                 // 10240
#define B_BYTES (PBN * ROW_B)                 // 20480
#define STG_B (A_BYTES + B_BYTES)             // 30720
#define SMEM_BYTES (STAGES * STG_B)           // 153600

template<bool SCALE>
__global__ void __launch_bounds__(256, 1)
gemm_h(const __half* __restrict__ A, const __half* __restrict__ Wt,
       const float* __restrict__ bias, const float* __restrict__ gains,
       float strength, float* __restrict__ C, int M, int N, int K)
{
    extern __shared__ __align__(16) char sm[];
    const uint32_t sbase = smem_u32(sm);

    const int tid = threadIdx.x;
    const int bm0 = blockIdx.x * PBM;
    const int bn0 = blockIdx.y * PBN;

    // ---- copy mapping: 4 threads per row, 16B chunks along K ----
    const int crow  = tid >> 2;               // 0..63
    const int cchk  = tid & 3;                // 16B chunk in row
    const __half* ag = A  + (size_t)(bm0 + crow) * K + cchk * 8;
    const __half* bg = Wt + (size_t)(bn0 + crow) * K + cchk * 8;
    const size_t aRowStep = (size_t)64 * K;   // 64 rows per pass

    const int niter = K / PBK;

    auto issue = [&](int stage, int k0) {
        const uint32_t sa = sbase + stage * STG_B;
        #pragma unroll
        for (int j = 0; j < 2; j++)            // A: 128 rows
            cp16(sa + (crow + 64 * j) * ROW_B + cchk * 16,
                 ag + (size_t)j * aRowStep + k0);
        const uint32_t sb = sa + A_BYTES;
        #pragma unroll
        for (int j = 0; j < 4; j++)            // B: 256 rows
            cp16(sb + (crow + 64 * j) * ROW_B + cchk * 16,
                 bg + (size_t)j * aRowStep + k0);
    };

    // ---- mma mapping: 8 warps 2m x 4n, warp tile 64x64 ----
    const int lane = tid & 31;
    const int wid  = tid >> 5;
    const int wm   = (wid & 1) * 64;
    const int wn   = (wid >> 1) * 64;
    const int ar   = lane >> 2;                // 0..7
    const int ac   = lane & 3;                 // 0..3

    float acc[4][8][4];
    #pragma unroll
    for (int mi = 0; mi < 4; mi++)
        #pragma unroll
        for (int ni = 0; ni < 8; ni++)
            #pragma unroll
            for (int j = 0; j < 4; j++) acc[mi][ni][j] = 0.f;

    #pragma unroll
    for (int s = 0; s < STAGES - 1; s++) {
        if (s < niter) issue(s, s * PBK);
        cp_commit();
    }

    for (int kt = 0; kt < niter; kt++) {
        cp_wait<STAGES - 2>();
        __syncthreads();

        const int nk = kt + STAGES - 1;
        if (nk < niter) issue(nk % STAGES, nk * PBK);
        cp_commit();

        const uint32_t* as = (const uint32_t*)(sm + (size_t)(kt % STAGES) * STG_B);
        const uint32_t* bs = (const uint32_t*)(sm + (size_t)(kt % STAGES) * STG_B + A_BYTES);

        #pragma unroll
        for (int ks = 0; ks < PBK; ks += 16) {
            const int kw = ks >> 1;            // word offset within row
            unsigned a[4][4], b[8][2];
            #pragma unroll
            for (int mi = 0; mi < 4; mi++) {
                const uint32_t* ap = as + (wm + mi * 16 + ar) * 20 + kw + ac;
                a[mi][0] = ap[0];
                a[mi][1] = ap[8 * 20];
                a[mi][2] = ap[4];
                a[mi][3] = ap[8 * 20 + 4];
            }
            #pragma unroll
            for (int ni = 0; ni < 8; ni++) {
                const uint32_t* bp = bs + (wn + ni * 8 + ar) * 20 + kw + ac;
                b[ni][0] = bp[0];
                b[ni][1] = bp[4];
            }
            #pragma unroll
            for (int mi = 0; mi < 4; mi++)
                #pragma unroll
                for (int ni = 0; ni < 8; ni++)
                    mma16(acc[mi][ni], a[mi], b[ni]);
        }
    }

    // ---- epilogue: bias + optional row scale ----
    #pragma unroll
    for (int mi = 0; mi < 4; mi++) {
        const int r0 = bm0 + wm + mi * 16 + ar;
        const int r1 = r0 + 8;
        float s0 = 1.f, s1 = 1.f;
        if (SCALE) {
            s0 = 1.f + strength * (gains[r0] - 1.f);
            s1 = 1.f + strength * (gains[r1] - 1.f);
        }
        #pragma unroll
        for (int ni = 0; ni < 8; ni++) {
            const int col = bn0 + wn + ni * 8 + ac * 2;
            const float b0 = bias[col], b1 = bias[col + 1];
            float2 o0, o1;
            o0.x = (acc[mi][ni][0] + b0) * s0;
            o0.y = (acc[mi][ni][1] + b1) * s0;
            o1.x = (acc[mi][ni][2] + b0) * s1;
            o1.y = (acc[mi][ni][3] + b1) * s1;
            *(float2*)&C[(size_t)r0 * N + col] = o0;
            *(float2*)&C[(size_t)r1 * N + col] = o1;
        }
    }
}

// ---------------------------------------------------------------------------
// GIF scan: cur (f32, in) -> spikes (fp16, out); sequential over S per channel
// ---------------------------------------------------------------------------
__global__ void gif_scan(const float* __restrict__ cur, __half* __restrict__ spk, int D)
{
    const int t = blockIdx.x * blockDim.x + threadIdx.x;
    if (t >= B_ * D) return;
    const int b = t / D, d = t % D;
    const float* p = cur + (size_t)b * S_ * D + d;
    __half* q = spk + (size_t)b * S_ * D + d;

    const float KX = 4.0f * 1.4426950408889634f;  // 4*log2(e)
    float v = 0.f;
    #pragma unroll 1
    for (int s0 = 0; s0 < S_; s0 += 8) {
        float c[8];
        #pragma unroll
        for (int i = 0; i < 8; i++) c[i] = p[(size_t)(s0 + i) * D];
        #pragma unroll
        for (int i = 0; i < 8; i++) {
            v = fmaf(DECAY, v, c[i]);
            const float e  = fast_ex2(fmaf(-KX, v, KX));   // exp(-4(v-1))
            const float sp = fast_rcp(1.0f + e);
            q[(size_t)(s0 + i) * D] = __float2half_rn(sp);
            v -= sp;
        }
    }
}

// ---------------------------------------------------------------------------
// launch
// ---------------------------------------------------------------------------
extern "C" void kernel_launch(void* const* d_in, const int* in_sizes, int n_in,
                              void* d_out, int out_size)
{
    const void*  ids   = d_in[0];
    const float* gains = (const float*)d_in[1];
    const float* emb   = (const float*)d_in[2];
    const float* encW  = (const float*)d_in[3];
    const float* encb  = (const float*)d_in[4];
    const float* decW  = (const float*)d_in[5];
    const float* decb  = (const float*)d_in[6];
    const float* outW  = (const float*)d_in[7];
    const float* outb  = (const float*)d_in[8];
    float* out = (float*)d_out;

    float  *buf1, *buf2;
    __half *s1h, *s2h, *embH, *encWt, *decWt, *outWt;
    cudaGetSymbolAddress((void**)&buf1,  g_buf1);
    cudaGetSymbolAddress((void**)&buf2,  g_buf2);
    cudaGetSymbolAddress((void**)&s1h,   g_s1h);
    cudaGetSymbolAddress((void**)&s2h,   g_s2h);
    cudaGetSymbolAddress((void**)&embH,  g_embH);
    cudaGetSymbolAddress((void**)&encWt, g_encWt);
    cudaGetSymbolAddress((void**)&decWt, g_decWt);
    cudaGetSymbolAddress((void**)&outWt, g_outWt);

    cudaFuncSetAttribute(gemm_h<true>,  cudaFuncAttributeMaxDynamicSharedMemorySize, SMEM_BYTES);
    cudaFuncSetAttribute(gemm_h<false>, cudaFuncAttributeMaxDynamicSharedMemorySize, SMEM_BYTES);

    sniff_ids<<<1, 32>>>((const int*)ids);

    // fp16 operand prep
    gather_h<<<M_, 256>>>(emb, ids, embH);
    conv_transpose<<<dim3(H_/32, E_/32), dim3(32, 8)>>>(encW, encWt, E_, H_);
    conv_transpose<<<dim3(E_/32, H_/32), dim3(32, 8)>>>(decW, decWt, H_, E_);
    conv_transpose<<<dim3(V_/32, E_/32), dim3(32, 8)>>>(outW, outWt, E_, V_);

    // enc: cur1 = (embH @ encW + encb) * (1+0.3*(g-1))    [4096 x 2048, K=1024]
    gemm_h<true><<<dim3(M_/PBM, H_/PBN), 256, SMEM_BYTES>>>(
        embH, encWt, encb, gains, 0.3f, buf1, M_, H_, E_);
    gif_scan<<<(B_*H_ + 127) / 128, 128>>>(buf1, s1h, H_);

    // dec: cur2 = (spikes1 @ decW + decb) * (1+0.2*(g-1)) [4096 x 1024, K=2048]
    gemm_h<true><<<dim3(M_/PBM, E_/PBN), 256, SMEM_BYTES>>>(
        s1h, decWt, decb, gains, 0.2f, buf2, M_, E_, H_);
    gif_scan<<<(B_*E_ + 127) / 128, 128>>>(buf2, s2h, E_);

    // out: logits = spikes2 @ outW + outb                 [4096 x 32000, K=1024]
    gemm_h<false><<<dim3(M_/PBM, V_/PBN), 256, SMEM_BYTES>>>(
        s2h, outWt, outb, nullptr, 0.f, out, M_, V_, E_);
}

// round 5
// speedup vs baseline: 1.4928x; 1.4804x over previous
#include <cuda_runtime.h>
#include <cuda_fp16.h>
#include <cstdint>
#include <cstddef>

#define DECAY 0.9f

#define B_ 2
#define S_ 2048
#define V_ 32000
#define E_ 1024
#define H_ 2048
#define M_ (B_*S_)   // 4096 rows

// Scratch (allocation-free rule: device globals)
__device__ float  g_buf1[(size_t)M_ * H_];    // 32 MB: cur1 (f32)
__device__ float  g_buf2[(size_t)M_ * E_];    // 16 MB: cur2 (f32)
__device__ __half g_s1h [(size_t)M_ * H_];    // 16 MB: spikes1 (fp16)
__device__ __half g_s2h [(size_t)M_ * E_];    //  8 MB: spikes2 (fp16)
__device__ __half g_embH[(size_t)M_ * E_];    //  8 MB: gathered embeddings (fp16)
__device__ __half g_encWt[(size_t)H_ * E_];   //  4 MB: enc_W^T  [H][E]
__device__ __half g_decWt[(size_t)E_ * H_];   //  4 MB: dec_W^T  [E][H]
__device__ __half g_outWt[(size_t)V_ * E_];   // 64 MB: out_W^T  [V][E]
__device__ int    g_ids_is64;

// ---------------------------------------------------------------------------
// helpers
// ---------------------------------------------------------------------------
__device__ __forceinline__ float fast_ex2(float x) {
    float y; asm("ex2.approx.f32 %0, %1;" : "=f"(y) : "f"(x)); return y;
}
__device__ __forceinline__ float fast_rcp(float x) {
    float y; asm("rcp.approx.f32 %0, %1;" : "=f"(y) : "f"(x)); return y;
}
__device__ __forceinline__ void mma16(float* c, const unsigned* a, const unsigned* b) {
    asm volatile(
        "mma.sync.aligned.m16n8k16.row.col.f32.f16.f16.f32 "
        "{%0,%1,%2,%3}, {%4,%5,%6,%7}, {%8,%9}, {%0,%1,%2,%3};\n"
        : "+f"(c[0]), "+f"(c[1]), "+f"(c[2]), "+f"(c[3])
        : "r"(a[0]), "r"(a[1]), "r"(a[2]), "r"(a[3]), "r"(b[0]), "r"(b[1]));
}
__device__ __forceinline__ uint32_t smem_u32(const void* p) {
    uint32_t a;
    asm("{ .reg .u64 t; cvta.to.shared.u64 t, %1; cvt.u32.u64 %0, t; }" : "=r"(a) : "l"(p));
    return a;
}
__device__ __forceinline__ void cp16(uint32_t s, const void* g) {
    asm volatile("cp.async.cg.shared.global [%0], [%1], 16;" :: "r"(s), "l"(g) : "memory");
}
__device__ __forceinline__ void cp_commit() {
    asm volatile("cp.async.commit_group;" ::: "memory");
}
template<int N>
__device__ __forceinline__ void cp_wait() {
    asm volatile("cp.async.wait_group %0;" :: "n"(N) : "memory");
}

// ---------------------------------------------------------------------------
// dtype sniffer for input_ids (int32 vs int64)
// ---------------------------------------------------------------------------
__global__ void sniff_ids(const int* __restrict__ ids32) {
    if (threadIdx.x == 0 && blockIdx.x == 0) {
        int zeros = 0;
        for (int i = 1; i < 255; i += 2) zeros += (ids32[i] == 0);
        g_ids_is64 = (zeros > 64) ? 1 : 0;
    }
}

// ---------------------------------------------------------------------------
// weight transpose + fp32->fp16:  W[K][N] -> Wt[N][K]
// ---------------------------------------------------------------------------
__global__ void conv_transpose(const float* __restrict__ W, __half* __restrict__ Wt,
                               int K, int N)
{
    __shared__ float t[32][33];
    const int k0 = blockIdx.y * 32, n0 = blockIdx.x * 32;
    const int tx = threadIdx.x, ty = threadIdx.y;   // 32 x 8
    #pragma unroll
    for (int i = 0; i < 32; i += 8)
        t[ty + i][tx] = W[(size_t)(k0 + ty + i) * N + n0 + tx];
    __syncthreads();
    #pragma unroll
    for (int i = 0; i < 32; i += 8)
        Wt[(size_t)(n0 + ty + i) * K + k0 + tx] = __float2half_rn(t[tx][ty + i]);
}

// ---------------------------------------------------------------------------
// embedding gather -> fp16
// ---------------------------------------------------------------------------
__global__ void gather_h(const float* __restrict__ emb, const void* __restrict__ idsv,
                         __half* __restrict__ dst)
{
    const int row = blockIdx.x;
    long long id = g_ids_is64 ? ((const long long*)idsv)[row]
                              : (long long)((const int*)idsv)[row];
    const float4* s = (const float4*)(emb + (size_t)id * E_);
    __half2* d = (__half2*)(dst + (size_t)row * E_);
    const int c = threadIdx.x;            // 256 threads, E/4 = 256 float4
    float4 v = s[c];
    d[2*c]   = __floats2half2_rn(v.x, v.y);
    d[2*c+1] = __floats2half2_rn(v.z, v.w);
}

// ---------------------------------------------------------------------------
// fp16 NT GEMM:  C[M,N](f32) = (A[M,K](h) @ Wt[N,K](h)^T + bias) * rowscale
// Block 128x256x32, 5-stage cp.async, 8 warps (2m x 4n), warp 64x64,
// mma.m16n8k16. SMEM rows: pitch 40 halfs (80B) => conflict-free .b32 frags.
// Requires M%128==0, N%256==0, K%32==0.
// ---------------------------------------------------------------------------
#define PBM 128
#define PBN 256
#define PBK 32
#define STAGES 5
#define ROW_B 80                              // bytes per smem row (40 halfs)
#define A_BYTES (PBM * ROW_B)                 // 10240
#define B_BYTES (PBN * ROW_B)                 // 20480
#define STG_B (A_BYTES + B_BYTES)             // 30720
#define SMEM_BYTES (STAGES * STG_B)           // 153600

template<bool SCALE>
__global__ void __launch_bounds__(256, 1)
gemm_h(const __half* __restrict__ A, const __half* __restrict__ Wt,
       const float* __restrict__ bias, const float* __restrict__ gains,
       float strength, float* __restrict__ C, int M, int N, int K)
{
    extern __shared__ __align__(16) char sm[];
    const uint32_t sbase = smem_u32(sm);

    const int tid = threadIdx.x;
    const int bm0 = blockIdx.x * PBM;
    const int bn0 = blockIdx.y * PBN;

    // ---- copy mapping: 4 threads per row, 16B chunks along K ----
    const int crow  = tid >> 2;               // 0..63
    const int cchk  = tid & 3;                // 16B chunk in row
    const __half* ag = A  + (size_t)(bm0 + crow) * K + cchk * 8;
    const __half* bg = Wt + (size_t)(bn0 + crow) * K + cchk * 8;
    const size_t aRowStep = (size_t)64 * K;   // 64 rows per pass

    const int niter = K / PBK;

    auto issue = [&](int stage, int k0) {
        const uint32_t sa = sbase + stage * STG_B;
        #pragma unroll
        for (int j = 0; j < 2; j++)            // A: 128 rows
            cp16(sa + (crow + 64 * j) * ROW_B + cchk * 16,
                 ag + (size_t)j * aRowStep + k0);
        const uint32_t sb = sa + A_BYTES;
        #pragma unroll
        for (int j = 0; j < 4; j++)            // B: 256 rows
            cp16(sb + (crow + 64 * j) * ROW_B + cchk * 16,
                 bg + (size_t)j * aRowStep + k0);
    };

    // ---- mma mapping: 8 warps 2m x 4n, warp tile 64x64 ----
    const int lane = tid & 31;
    const int wid  = tid >> 5;
    const int wm   = (wid & 1) * 64;
    const int wn   = (wid >> 1) * 64;
    const int ar   = lane >> 2;                // 0..7
    const int ac   = lane & 3;                 // 0..3

    float acc[4][8][4];
    #pragma unroll
    for (int mi = 0; mi < 4; mi++)
        #pragma unroll
        for (int ni = 0; ni < 8; ni++)
            #pragma unroll
            for (int j = 0; j < 4; j++) acc[mi][ni][j] = 0.f;

    #pragma unroll
    for (int s = 0; s < STAGES - 1; s++) {
        if (s < niter) issue(s, s * PBK);
        cp_commit();
    }

    for (int kt = 0; kt < niter; kt++) {
        cp_wait<STAGES - 2>();
        __syncthreads();

        const int nk = kt + STAGES - 1;
        if (nk < niter) issue(nk % STAGES, nk * PBK);
        cp_commit();

        const uint32_t* as = (const uint32_t*)(sm + (size_t)(kt % STAGES) * STG_B);
        const uint32_t* bs = (const uint32_t*)(sm + (size_t)(kt % STAGES) * STG_B + A_BYTES);

        #pragma unroll
        for (int ks = 0; ks < PBK; ks += 16) {
            const int kw = ks >> 1;            // word offset within row
            unsigned a[4][4], b[8][2];
            #pragma unroll
            for (int mi = 0; mi < 4; mi++) {
                const uint32_t* ap = as + (wm + mi * 16 + ar) * 20 + kw + ac;
                a[mi][0] = ap[0];
                a[mi][1] = ap[8 * 20];
                a[mi][2] = ap[4];
                a[mi][3] = ap[8 * 20 + 4];
            }
            #pragma unroll
            for (int ni = 0; ni < 8; ni++) {
                const uint32_t* bp = bs + (wn + ni * 8 + ar) * 20 + kw + ac;
                b[ni][0] = bp[0];
                b[ni][1] = bp[4];
            }
            #pragma unroll
            for (int mi = 0; mi < 4; mi++)
                #pragma unroll
                for (int ni = 0; ni < 8; ni++)
                    mma16(acc[mi][ni], a[mi], b[ni]);
        }
    }

    // ---- epilogue: bias + optional row scale ----
    #pragma unroll
    for (int mi = 0; mi < 4; mi++) {
        const int r0 = bm0 + wm + mi * 16 + ar;
        const int r1 = r0 + 8;
        float s0 = 1.f, s1 = 1.f;
        if (SCALE) {
            s0 = 1.f + strength * (gains[r0] - 1.f);
            s1 = 1.f + strength * (gains[r1] - 1.f);
        }
        #pragma unroll
        for (int ni = 0; ni < 8; ni++) {
            const int col = bn0 + wn + ni * 8 + ac * 2;
            const float b0 = bias[col], b1 = bias[col + 1];
            float2 o0, o1;
            o0.x = (acc[mi][ni][0] + b0) * s0;
            o0.y = (acc[mi][ni][1] + b1) * s0;
            o1.x = (acc[mi][ni][2] + b0) * s1;
            o1.y = (acc[mi][ni][3] + b1) * s1;
            *(float2*)&C[(size_t)r0 * N + col] = o0;
            *(float2*)&C[(size_t)r1 * N + col] = o1;
        }
    }
}

// ---------------------------------------------------------------------------
// GIF scan: cur (f32, in) -> spikes (fp16, out); sequential over S per channel
// ---------------------------------------------------------------------------
__global__ void gif_scan(const float* __restrict__ cur, __half* __restrict__ spk, int D)
{
    const int t = blockIdx.x * blockDim.x + threadIdx.x;
    if (t >= B_ * D) return;
    const int b = t / D, d = t % D;
    const float* p = cur + (size_t)b * S_ * D + d;
    __half* q = spk + (size_t)b * S_ * D + d;

    const float KX = 4.0f * 1.4426950408889634f;  // 4*log2(e)
    float v = 0.f;
    #pragma unroll 1
    for (int s0 = 0; s0 < S_; s0 += 8) {
        float c[8];
        #pragma unroll
        for (int i = 0; i < 8; i++) c[i] = p[(size_t)(s0 + i) * D];
        #pragma unroll
        for (int i = 0; i < 8; i++) {
            v = fmaf(DECAY, v, c[i]);
            const float e  = fast_ex2(fmaf(-KX, v, KX));   // exp(-4(v-1))
            const float sp = fast_rcp(1.0f + e);
            q[(size_t)(s0 + i) * D] = __float2half_rn(sp);
            v -= sp;
        }
    }
}

// ---------------------------------------------------------------------------
// launch
// ---------------------------------------------------------------------------
extern "C" void kernel_launch(void* const* d_in, const int* in_sizes, int n_in,
                              void* d_out, int out_size)
{
    const void*  ids   = d_in[0];
    const float* gains = (const float*)d_in[1];
    const float* emb   = (const float*)d_in[2];
    const float* encW  = (const float*)d_in[3];
    const float* encb  = (const float*)d_in[4];
    const float* decW  = (const float*)d_in[5];
    const float* decb  = (const float*)d_in[6];
    const float* outW  = (const float*)d_in[7];
    const float* outb  = (const float*)d_in[8];
    float* out = (float*)d_out;

    float  *buf1, *buf2;
    __half *s1h, *s2h, *embH, *encWt, *decWt, *outWt;
    cudaGetSymbolAddress((void**)&buf1,  g_buf1);
    cudaGetSymbolAddress((void**)&buf2,  g_buf2);
    cudaGetSymbolAddress((void**)&s1h,   g_s1h);
    cudaGetSymbolAddress((void**)&s2h,   g_s2h);
    cudaGetSymbolAddress((void**)&embH,  g_embH);
    cudaGetSymbolAddress((void**)&encWt, g_encWt);
    cudaGetSymbolAddress((void**)&decWt, g_decWt);
    cudaGetSymbolAddress((void**)&outWt, g_outWt);

    cudaFuncSetAttribute(gemm_h<true>,  cudaFuncAttributeMaxDynamicSharedMemorySize, SMEM_BYTES);
    cudaFuncSetAttribute(gemm_h<false>, cudaFuncAttributeMaxDynamicSharedMemorySize, SMEM_BYTES);

    sniff_ids<<<1, 32>>>((const int*)ids);

    // fp16 operand prep
    gather_h<<<M_, 256>>>(emb, ids, embH);
    conv_transpose<<<dim3(H_/32, E_/32), dim3(32, 8)>>>(encW, encWt, E_, H_);
    conv_transpose<<<dim3(E_/32, H_/32), dim3(32, 8)>>>(decW, decWt, H_, E_);
    conv_transpose<<<dim3(V_/32, E_/32), dim3(32, 8)>>>(outW, outWt, E_, V_);

    // enc: cur1 = (embH @ encW + encb) * (1+0.3*(g-1))    [4096 x 2048, K=1024]
    gemm_h<true><<<dim3(M_/PBM, H_/PBN), 256, SMEM_BYTES>>>(
        embH, encWt, encb, gains, 0.3f, buf1, M_, H_, E_);
    gif_scan<<<(B_*H_ + 127) / 128, 128>>>(buf1, s1h, H_);

    // dec: cur2 = (spikes1 @ decW + decb) * (1+0.2*(g-1)) [4096 x 1024, K=2048]
    gemm_h<true><<<dim3(M_/PBM, E_/PBN), 256, SMEM_BYTES>>>(
        s1h, decWt, decb, gains, 0.2f, buf2, M_, E_, H_);
    gif_scan<<<(B_*E_ + 127) / 128, 128>>>(buf2, s2h, E_);

    // out: logits = spikes2 @ outW + outb                 [4096 x 32000, K=1024]
    gemm_h<false><<<dim3(M_/PBM, V_/PBN), 256, SMEM_BYTES>>>(
        s2h, outWt, outb, nullptr, 0.f, out, M_, V_, E_);
}

// round 6
// speedup vs baseline: 1.4928x; 1.0001x over previous
#include <cuda_runtime.h>
#include <cuda_fp16.h>
#include <cstdint>
#include <cstddef>

#define DECAY 0.9f

#define B_ 2
#define S_ 2048
#define V_ 32000
#define E_ 1024
#define H_ 2048
#define M_ (B_*S_)   // 4096 rows

// Scratch (allocation-free rule: device globals)
__device__ float  g_buf1[(size_t)M_ * H_];    // 32 MB: cur1 (f32)
__device__ float  g_buf2[(size_t)M_ * E_];    // 16 MB: cur2 (f32)
__device__ __half g_s1h [(size_t)M_ * H_];    // 16 MB: spikes1 (fp16)
__device__ __half g_s2h [(size_t)M_ * E_];    //  8 MB: spikes2 (fp16)
__device__ __half g_embH[(size_t)M_ * E_];    //  8 MB: gathered embeddings (fp16)
__device__ __half g_encWt[(size_t)H_ * E_];   //  4 MB: enc_W^T  [H][E]
__device__ __half g_decWt[(size_t)E_ * H_];   //  4 MB: dec_W^T  [E][H]
__device__ __half g_outWt[(size_t)V_ * E_];   // 64 MB: out_W^T  [V][E]
__device__ int    g_ids_is64;

// ---------------------------------------------------------------------------
// helpers
// ---------------------------------------------------------------------------
__device__ __forceinline__ float fast_ex2(float x) {
    float y; asm("ex2.approx.f32 %0, %1;" : "=f"(y) : "f"(x)); return y;
}
__device__ __forceinline__ float fast_rcp(float x) {
    float y; asm("rcp.approx.f32 %0, %1;" : "=f"(y) : "f"(x)); return y;
}
__device__ __forceinline__ void mma16(float* c, const unsigned* a, const unsigned* b) {
    asm volatile(
        "mma.sync.aligned.m16n8k16.row.col.f32.f16.f16.f32 "
        "{%0,%1,%2,%3}, {%4,%5,%6,%7}, {%8,%9}, {%0,%1,%2,%3};\n"
        : "+f"(c[0]), "+f"(c[1]), "+f"(c[2]), "+f"(c[3])
        : "r"(a[0]), "r"(a[1]), "r"(a[2]), "r"(a[3]), "r"(b[0]), "r"(b[1]));
}
__device__ __forceinline__ uint32_t smem_u32(const void* p) {
    uint32_t a;
    asm("{ .reg .u64 t; cvta.to.shared.u64 t, %1; cvt.u32.u64 %0, t; }" : "=r"(a) : "l"(p));
    return a;
}
__device__ __forceinline__ void cp16(uint32_t s, const void* g) {
    asm volatile("cp.async.cg.shared.global [%0], [%1], 16;" :: "r"(s), "l"(g) : "memory");
}
__device__ __forceinline__ void cp_commit() {
    asm volatile("cp.async.commit_group;" ::: "memory");
}
template<int N>
__device__ __forceinline__ void cp_wait() {
    asm volatile("cp.async.wait_group %0;" :: "n"(N) : "memory");
}

// ---------------------------------------------------------------------------
// dtype sniffer for input_ids (int32 vs int64)
// ---------------------------------------------------------------------------
__global__ void sniff_ids(const int* __restrict__ ids32) {
    if (threadIdx.x == 0 && blockIdx.x == 0) {
        int zeros = 0;
        for (int i = 1; i < 255; i += 2) zeros += (ids32[i] == 0);
        g_ids_is64 = (zeros > 64) ? 1 : 0;
    }
}

// ---------------------------------------------------------------------------
// weight transpose + fp32->fp16:  W[K][N] -> Wt[N][K]
// ---------------------------------------------------------------------------
__global__ void conv_transpose(const float* __restrict__ W, __half* __restrict__ Wt,
                               int K, int N)
{
    __shared__ float t[32][33];
    const int k0 = blockIdx.y * 32, n0 = blockIdx.x * 32;
    const int tx = threadIdx.x, ty = threadIdx.y;   // 32 x 8
    #pragma unroll
    for (int i = 0; i < 32; i += 8)
        t[ty + i][tx] = W[(size_t)(k0 + ty + i) * N + n0 + tx];
    __syncthreads();
    #pragma unroll
    for (int i = 0; i < 32; i += 8)
        Wt[(size_t)(n0 + ty + i) * K + k0 + tx] = __float2half_rn(t[tx][ty + i]);
}

// ---------------------------------------------------------------------------
// embedding gather -> fp16
// ---------------------------------------------------------------------------
__global__ void gather_h(const float* __restrict__ emb, const void* __restrict__ idsv,
                         __half* __restrict__ dst)
{
    const int row = blockIdx.x;
    long long id = g_ids_is64 ? ((const long long*)idsv)[row]
                              : (long long)((const int*)idsv)[row];
    const float4* s = (const float4*)(emb + (size_t)id * E_);
    __half2* d = (__half2*)(dst + (size_t)row * E_);
    const int c = threadIdx.x;            // 256 threads, E/4 = 256 float4
    float4 v = s[c];
    d[2*c]   = __floats2half2_rn(v.x, v.y);
    d[2*c+1] = __floats2half2_rn(v.z, v.w);
}

// ---------------------------------------------------------------------------
// fp16 NT GEMM:  C[M,N](f32) = (A[M,K](h) @ Wt[N,K](h)^T + bias) * rowscale
// Block 128x256x32, 5-stage cp.async, 8 warps (2m x 4n), warp 64x64,
// mma.m16n8k16. SMEM rows: pitch 40 halfs (80B) => conflict-free .b32 frags.
// Requires M%128==0, N%256==0, K%32==0.
// ---------------------------------------------------------------------------
#define PBM 128
#define PBN 256
#define PBK 32
#define STAGES 5
#define ROW_B 80                              // bytes per smem row (40 halfs)
#define A_BYTES (PBM * ROW_B)                 // 10240
#define B_BYTES (PBN * ROW_B)                 // 20480
#define STG_B (A_BYTES + B_BYTES)             // 30720
#define SMEM_BYTES (STAGES * STG_B)           // 153600

template<bool SCALE>
__global__ void __launch_bounds__(256, 1)
gemm_h(const __half* __restrict__ A, const __half* __restrict__ Wt,
       const float* __restrict__ bias, const float* __restrict__ gains,
       float strength, float* __restrict__ C, int M, int N, int K)
{
    extern __shared__ __align__(16) char sm[];
    const uint32_t sbase = smem_u32(sm);

    const int tid = threadIdx.x;
    const int bm0 = blockIdx.x * PBM;
    const int bn0 = blockIdx.y * PBN;

    // ---- copy mapping: 4 threads per row, 16B chunks along K ----
    const int crow  = tid >> 2;               // 0..63
    const int cchk  = tid & 3;                // 16B chunk in row
    const __half* ag = A  + (size_t)(bm0 + crow) * K + cchk * 8;
    const __half* bg = Wt + (size_t)(bn0 + crow) * K + cchk * 8;
    const size_t aRowStep = (size_t)64 * K;   // 64 rows per pass

    const int niter = K / PBK;

    auto issue = [&](int stage, int k0) {
        const uint32_t sa = sbase + stage * STG_B;
        #pragma unroll
        for (int j = 0; j < 2; j++)            // A: 128 rows
            cp16(sa + (crow + 64 * j) * ROW_B + cchk * 16,
                 ag + (size_t)j * aRowStep + k0);
        const uint32_t sb = sa + A_BYTES;
        #pragma unroll
        for (int j = 0; j < 4; j++)            // B: 256 rows
            cp16(sb + (crow + 64 * j) * ROW_B + cchk * 16,
                 bg + (size_t)j * aRowStep + k0);
    };

    // ---- mma mapping: 8 warps 2m x 4n, warp tile 64x64 ----
    const int lane = tid & 31;
    const int wid  = tid >> 5;
    const int wm   = (wid & 1) * 64;
    const int wn   = (wid >> 1) * 64;
    const int ar   = lane >> 2;                // 0..7
    const int ac   = lane & 3;                 // 0..3

    float acc[4][8][4];
    #pragma unroll
    for (int mi = 0; mi < 4; mi++)
        #pragma unroll
        for (int ni = 0; ni < 8; ni++)
            #pragma unroll
            for (int j = 0; j < 4; j++) acc[mi][ni][j] = 0.f;

    #pragma unroll
    for (int s = 0; s < STAGES - 1; s++) {
        if (s < niter) issue(s, s * PBK);
        cp_commit();
    }

    for (int kt = 0; kt < niter; kt++) {
        cp_wait<STAGES - 2>();
        __syncthreads();

        const int nk = kt + STAGES - 1;
        if (nk < niter) issue(nk % STAGES, nk * PBK);
        cp_commit();

        const uint32_t* as = (const uint32_t*)(sm + (size_t)(kt % STAGES) * STG_B);
        const uint32_t* bs = (const uint32_t*)(sm + (size_t)(kt % STAGES) * STG_B + A_BYTES);

        #pragma unroll
        for (int ks = 0; ks < PBK; ks += 16) {
            const int kw = ks >> 1;            // word offset within row
            unsigned a[4][4], b[8][2];
            #pragma unroll
            for (int mi = 0; mi < 4; mi++) {
                const uint32_t* ap = as + (wm + mi * 16 + ar) * 20 + kw + ac;
                a[mi][0] = ap[0];
                a[mi][1] = ap[8 * 20];
                a[mi][2] = ap[4];
                a[mi][3] = ap[8 * 20 + 4];
            }
            #pragma unroll
            for (int ni = 0; ni < 8; ni++) {
                const uint32_t* bp = bs + (wn + ni * 8 + ar) * 20 + kw + ac;
                b[ni][0] = bp[0];
                b[ni][1] = bp[4];
            }
            #pragma unroll
            for (int mi = 0; mi < 4; mi++)
                #pragma unroll
                for (int ni = 0; ni < 8; ni++)
                    mma16(acc[mi][ni], a[mi], b[ni]);
        }
    }

    // ---- epilogue: bias + optional row scale ----
    #pragma unroll
    for (int mi = 0; mi < 4; mi++) {
        const int r0 = bm0 + wm + mi * 16 + ar;
        const int r1 = r0 + 8;
        float s0 = 1.f, s1 = 1.f;
        if (SCALE) {
            s0 = 1.f + strength * (gains[r0] - 1.f);
            s1 = 1.f + strength * (gains[r1] - 1.f);
        }
        #pragma unroll
        for (int ni = 0; ni < 8; ni++) {
            const int col = bn0 + wn + ni * 8 + ac * 2;
            const float b0 = bias[col], b1 = bias[col + 1];
            float2 o0, o1;
            o0.x = (acc[mi][ni][0] + b0) * s0;
            o0.y = (acc[mi][ni][1] + b1) * s0;
            o1.x = (acc[mi][ni][2] + b0) * s1;
            o1.y = (acc[mi][ni][3] + b1) * s1;
            *(float2*)&C[(size_t)r0 * N + col] = o0;
            *(float2*)&C[(size_t)r1 * N + col] = o1;
        }
    }
}

// ---------------------------------------------------------------------------
// GIF scan: cur (f32, in) -> spikes (fp16, out); sequential over S per channel
// ---------------------------------------------------------------------------
__global__ void gif_scan(const float* __restrict__ cur, __half* __restrict__ spk, int D)
{
    const int t = blockIdx.x * blockDim.x + threadIdx.x;
    if (t >= B_ * D) return;
    const int b = t / D, d = t % D;
    const float* p = cur + (size_t)b * S_ * D + d;
    __half* q = spk + (size_t)b * S_ * D + d;

    const float KX = 4.0f * 1.4426950408889634f;  // 4*log2(e)
    float v = 0.f;
    #pragma unroll 1
    for (int s0 = 0; s0 < S_; s0 += 8) {
        float c[8];
        #pragma unroll
        for (int i = 0; i < 8; i++) c[i] = p[(size_t)(s0 + i) * D];
        #pragma unroll
        for (int i = 0; i < 8; i++) {
            v = fmaf(DECAY, v, c[i]);
            const float e  = fast_ex2(fmaf(-KX, v, KX));   // exp(-4(v-1))
            const float sp = fast_rcp(1.0f + e);
            q[(size_t)(s0 + i) * D] = __float2half_rn(sp);
            v -= sp;
        }
    }
}

// ---------------------------------------------------------------------------
// launch
// ---------------------------------------------------------------------------
extern "C" void kernel_launch(void* const* d_in, const int* in_sizes, int n_in,
                              void* d_out, int out_size)
{
    const void*  ids   = d_in[0];
    const float* gains = (const float*)d_in[1];
    const float* emb   = (const float*)d_in[2];
    const float* encW  = (const float*)d_in[3];
    const float* encb  = (const float*)d_in[4];
    const float* decW  = (const float*)d_in[5];
    const float* decb  = (const float*)d_in[6];
    const float* outW  = (const float*)d_in[7];
    const float* outb  = (const float*)d_in[8];
    float* out = (float*)d_out;

    float  *buf1, *buf2;
    __half *s1h, *s2h, *embH, *encWt, *decWt, *outWt;
    cudaGetSymbolAddress((void**)&buf1,  g_buf1);
    cudaGetSymbolAddress((void**)&buf2,  g_buf2);
    cudaGetSymbolAddress((void**)&s1h,   g_s1h);
    cudaGetSymbolAddress((void**)&s2h,   g_s2h);
    cudaGetSymbolAddress((void**)&embH,  g_embH);
    cudaGetSymbolAddress((void**)&encWt, g_encWt);
    cudaGetSymbolAddress((void**)&decWt, g_decWt);
    cudaGetSymbolAddress((void**)&outWt, g_outWt);

    cudaFuncSetAttribute(gemm_h<true>,  cudaFuncAttributeMaxDynamicSharedMemorySize, SMEM_BYTES);
    cudaFuncSetAttribute(gemm_h<false>, cudaFuncAttributeMaxDynamicSharedMemorySize, SMEM_BYTES);

    sniff_ids<<<1, 32>>>((const int*)ids);

    // fp16 operand prep
    gather_h<<<M_, 256>>>(emb, ids, embH);
    conv_transpose<<<dim3(H_/32, E_/32), dim3(32, 8)>>>(encW, encWt, E_, H_);
    conv_transpose<<<dim3(E_/32, H_/32), dim3(32, 8)>>>(decW, decWt, H_, E_);
    conv_transpose<<<dim3(V_/32, E_/32), dim3(32, 8)>>>(outW, outWt, E_, V_);

    // enc: cur1 = (embH @ encW + encb) * (1+0.3*(g-1))    [4096 x 2048, K=1024]
    gemm_h<true><<<dim3(M_/PBM, H_/PBN), 256, SMEM_BYTES>>>(
        embH, encWt, encb, gains, 0.3f, buf1, M_, H_, E_);
    gif_scan<<<(B_*H_ + 127) / 128, 128>>>(buf1, s1h, H_);

    // dec: cur2 = (spikes1 @ decW + decb) * (1+0.2*(g-1)) [4096 x 1024, K=2048]
    gemm_h<true><<<dim3(M_/PBM, E_/PBN), 256, SMEM_BYTES>>>(
        s1h, decWt, decb, gains, 0.2f, buf2, M_, E_, H_);
    gif_scan<<<(B_*E_ + 127) / 128, 128>>>(buf2, s2h, E_);

    // out: logits = spikes2 @ outW + outb                 [4096 x 32000, K=1024]
    gemm_h<false><<<dim3(M_/PBM, V_/PBN), 256, SMEM_BYTES>>>(
        s2h, outWt, outb, nullptr, 0.f, out, M_, V_, E_);
}

// round 7
// speedup vs baseline: 1.6501x; 1.1053x over previous
#include <cuda_runtime.h>
#include <cuda_fp16.h>
#include <cstdint>
#include <cstddef>

#define DECAY 0.9f

#define B_ 2
#define S_ 2048
#define V_ 32000
#define E_ 1024
#define H_ 2048
#define M_ (B_*S_)   // 4096 rows

// Scratch (allocation-free rule: device globals)
__device__ float  g_buf1[(size_t)M_ * H_];    // 32 MB: cur1 (f32)
__device__ float  g_buf2[(size_t)M_ * E_];    // 16 MB: cur2 (f32)
__device__ __half g_s1h [(size_t)M_ * H_];    // 16 MB: spikes1 (fp16)
__device__ __half g_s2h [(size_t)M_ * E_];    //  8 MB: spikes2 (fp16)
__device__ __half g_embH[(size_t)M_ * E_];    //  8 MB: gathered embeddings (fp16)
__device__ __half g_encWt[(size_t)H_ * E_];   //  4 MB: enc_W^T  [H][E]
__device__ __half g_decWt[(size_t)E_ * H_];   //  4 MB: dec_W^T  [E][H]
__device__ __half g_outWt[(size_t)V_ * E_];   // 64 MB: out_W^T  [V][E]
__device__ int    g_ids_is64;

// ---------------------------------------------------------------------------
// helpers
// ---------------------------------------------------------------------------
__device__ __forceinline__ float fast_ex2(float x) {
    float y; asm("ex2.approx.f32 %0, %1;" : "=f"(y) : "f"(x)); return y;
}
__device__ __forceinline__ float fast_rcp(float x) {
    float y; asm("rcp.approx.f32 %0, %1;" : "=f"(y) : "f"(x)); return y;
}
__device__ __forceinline__ void mma16(float* c, const unsigned* a, const unsigned* b) {
    asm volatile(
        "mma.sync.aligned.m16n8k16.row.col.f32.f16.f16.f32 "
        "{%0,%1,%2,%3}, {%4,%5,%6,%7}, {%8,%9}, {%0,%1,%2,%3};\n"
        : "+f"(c[0]), "+f"(c[1]), "+f"(c[2]), "+f"(c[3])
        : "r"(a[0]), "r"(a[1]), "r"(a[2]), "r"(a[3]), "r"(b[0]), "r"(b[1]));
}
__device__ __forceinline__ void ldsm4(unsigned& r0, unsigned& r1, unsigned& r2,
                                      unsigned& r3, uint32_t a) {
    asm volatile("ldmatrix.sync.aligned.m8n8.x4.shared.b16 {%0,%1,%2,%3}, [%4];"
                 : "=r"(r0), "=r"(r1), "=r"(r2), "=r"(r3) : "r"(a));
}
__device__ __forceinline__ uint32_t smem_u32(const void* p) {
    uint32_t a;
    asm("{ .reg .u64 t; cvta.to.shared.u64 t, %1; cvt.u32.u64 %0, t; }" : "=r"(a) : "l"(p));
    return a;
}
__device__ __forceinline__ void cp16(uint32_t s, const void* g) {
    asm volatile("cp.async.cg.shared.global [%0], [%1], 16;" :: "r"(s), "l"(g) : "memory");
}
__device__ __forceinline__ void cp_commit() {
    asm volatile("cp.async.commit_group;" ::: "memory");
}
template<int N>
__device__ __forceinline__ void cp_wait() {
    asm volatile("cp.async.wait_group %0;" :: "n"(N) : "memory");
}

// ---------------------------------------------------------------------------
// dtype sniffer for input_ids (int32 vs int64)
// ---------------------------------------------------------------------------
__global__ void sniff_ids(const int* __restrict__ ids32) {
    if (threadIdx.x == 0 && blockIdx.x == 0) {
        int zeros = 0;
        for (int i = 1; i < 255; i += 2) zeros += (ids32[i] == 0);
        g_ids_is64 = (zeros > 64) ? 1 : 0;
    }
}

// ---------------------------------------------------------------------------
// weight transpose + fp32->fp16:  W[K][N] -> Wt[N][K]
// 64x64 tile, 256 threads. float4 gmem loads, 16B half stores (coalesced).
// Requires K%64==0, N%64==0.
// ---------------------------------------------------------------------------
__global__ void conv_transpose(const float* __restrict__ W, __half* __restrict__ Wt,
                               int K, int N)
{
    __shared__ float ts[64][65];
    const int k0 = blockIdx.y * 64, n0 = blockIdx.x * 64;
    const int t  = threadIdx.x;

    // load: thread -> k rows t>>4 (+16 step), n cols (t&15)*4
    const int lk = t >> 4, ln = (t & 15) * 4;
    #pragma unroll
    for (int i = 0; i < 4; i++) {
        float4 v = *(const float4*)&W[(size_t)(k0 + lk + 16 * i) * N + n0 + ln];
        ts[lk + 16 * i][ln]     = v.x;
        ts[lk + 16 * i][ln + 1] = v.y;
        ts[lk + 16 * i][ln + 2] = v.z;
        ts[lk + 16 * i][ln + 3] = v.w;
    }
    __syncthreads();

    // store: thread -> n row t>>2, k chunk (t&3)*16; 2x 16B stores
    const int sn = t >> 2, sk = (t & 3) * 16;
    uint4 o[2];
    __half2* oh = (__half2*)o;
    #pragma unroll
    for (int j = 0; j < 8; j++)
        oh[j] = __floats2half2_rn(ts[sk + 2*j][sn], ts[sk + 2*j + 1][sn]);
    uint4* dst = (uint4*)&Wt[(size_t)(n0 + sn) * K + k0 + sk];
    dst[0] = o[0];
    dst[1] = o[1];
}

// ---------------------------------------------------------------------------
// embedding gather -> fp16
// ---------------------------------------------------------------------------
__global__ void gather_h(const float* __restrict__ emb, const void* __restrict__ idsv,
                         __half* __restrict__ dst)
{
    const int row = blockIdx.x;
    long long id = g_ids_is64 ? ((const long long*)idsv)[row]
                              : (long long)((const int*)idsv)[row];
    const float4* s = (const float4*)(emb + (size_t)id * E_);
    __half2* d = (__half2*)(dst + (size_t)row * E_);
    const int c = threadIdx.x;            // 256 threads, E/4 = 256 float4
    float4 v = s[c];
    d[2*c]   = __floats2half2_rn(v.x, v.y);
    d[2*c+1] = __floats2half2_rn(v.z, v.w);
}

// ---------------------------------------------------------------------------
// fp16 NT GEMM:  C[M,N](f32) = (A[M,K](h) @ Wt[N,K](h)^T + bias) * rowscale
// Block 128x256x32, 5-stage cp.async, 8 warps (2m x 4n), warp 64x64,
// mma.m16n8k16 with ldmatrix.x4 fragment loads.
// SMEM rows: pitch 40 halfs (80B) => LDSM conflict-free.
// Requires M%128==0, N%256==0, K%32==0.
// ---------------------------------------------------------------------------
#define PBM 128
#define PBN 256
#define PBK 32
#define STAGES 5
#define ROW_B 80                              // bytes per smem row (40 halfs)
#define A_BYTES (PBM * ROW_B)                 // 10240
#define B_BYTES (PBN * ROW_B)                 // 20480
#define STG_B (A_BYTES + B_BYTES)             // 30720
#define SMEM_BYTES (STAGES * STG_B)           // 153600

template<bool SCALE>
__global__ void __launch_bounds__(256, 1)
gemm_h(const __half* __restrict__ A, const __half* __restrict__ Wt,
       const float* __restrict__ bias, const float* __restrict__ gains,
       float strength, float* __restrict__ C, int M, int N, int K)
{
    extern __shared__ __align__(16) char sm[];
    const uint32_t sbase = smem_u32(sm);

    const int tid = threadIdx.x;
    const int bm0 = blockIdx.x * PBM;
    const int bn0 = blockIdx.y * PBN;

    // ---- copy mapping: 4 threads per row, 16B chunks along K ----
    const int crow  = tid >> 2;               // 0..63
    const int cchk  = tid & 3;                // 16B chunk in row
    const __half* ag = A  + (size_t)(bm0 + crow) * K + cchk * 8;
    const __half* bg = Wt + (size_t)(bn0 + crow) * K + cchk * 8;
    const size_t rowStep = (size_t)64 * K;

    const int niter = K / PBK;

    auto issue = [&](int stage, int k0) {
        const uint32_t sa = sbase + stage * STG_B;
        #pragma unroll
        for (int j = 0; j < 2; j++)            // A: 128 rows
            cp16(sa + (crow + 64 * j) * ROW_B + cchk * 16,
                 ag + (size_t)j * rowStep + k0);
        const uint32_t sb = sa + A_BYTES;
        #pragma unroll
        for (int j = 0; j < 4; j++)            // B: 256 rows
            cp16(sb + (crow + 64 * j) * ROW_B + cchk * 16,
                 bg + (size_t)j * rowStep + k0);
    };

    // ---- mma mapping: 8 warps 2m x 4n, warp tile 64x64 ----
    const int lane = tid & 31;
    const int wid  = tid >> 5;
    const int wm   = (wid & 1) * 64;
    const int wn   = (wid >> 1) * 64;
    const int ar   = lane >> 2;                // 0..7
    const int ac   = lane & 3;                 // 0..3

    // ldmatrix lane address offsets (within a stage)
    // A frag mi: m0=rows0-7 klo, m1=rows8-15 klo, m2=rows0-7 khi, m3=rows8-15 khi
    const int a_row16 = ((lane >> 3) & 1) * 8 + (lane & 7);
    const int a_koff  = (lane >> 4) * 8;              // halfs
    uint32_t aoff[4];
    #pragma unroll
    for (int mi = 0; mi < 4; mi++)
        aoff[mi] = (uint32_t)(wm + mi * 16 + a_row16) * ROW_B + a_koff * 2;
    // B frag pair p (ni=2p,2p+1): m0=rows(2p*8) klo, m1=rows(2p*8) khi,
    //                             m2=rows((2p+1)*8) klo, m3=khi
    const int b_rowsel = ((lane >> 4) & 1) * 8 + (lane & 7);
    const int b_koff   = ((lane >> 3) & 1) * 8;       // halfs
    uint32_t boff[4];
    #pragma unroll
    for (int p = 0; p < 4; p++)
        boff[p] = A_BYTES + (uint32_t)(wn + p * 16 + b_rowsel) * ROW_B + b_koff * 2;

    float acc[4][8][4];
    #pragma unroll
    for (int mi = 0; mi < 4; mi++)
        #pragma unroll
        for (int ni = 0; ni < 8; ni++)
            #pragma unroll
            for (int j = 0; j < 4; j++) acc[mi][ni][j] = 0.f;

    #pragma unroll
    for (int s = 0; s < STAGES - 1; s++) {
        if (s < niter) issue(s, s * PBK);
        cp_commit();
    }

    for (int kt = 0; kt < niter; kt++) {
        cp_wait<STAGES - 2>();
        __syncthreads();

        const int nk = kt + STAGES - 1;
        if (nk < niter) issue(nk % STAGES, nk * PBK);
        cp_commit();

        const uint32_t stb = sbase + (uint32_t)(kt % STAGES) * STG_B;

        #pragma unroll
        for (int ks = 0; ks < PBK; ks += 16) {
            const uint32_t kb = ks * 2;        // byte offset along K
            unsigned a[4][4], b[8][2];
            #pragma unroll
            for (int mi = 0; mi < 4; mi++)
                ldsm4(a[mi][0], a[mi][1], a[mi][2], a[mi][3], stb + aoff[mi] + kb);
            #pragma unroll
            for (int p = 0; p < 4; p++)
                ldsm4(b[2*p][0], b[2*p][1], b[2*p+1][0], b[2*p+1][1],
                      stb + boff[p] + kb);
            #pragma unroll
            for (int mi = 0; mi < 4; mi++)
                #pragma unroll
                for (int ni = 0; ni < 8; ni++)
                    mma16(acc[mi][ni], a[mi], b[ni]);
        }
    }

    // ---- epilogue: bias + optional row scale ----
    #pragma unroll
    for (int mi = 0; mi < 4; mi++) {
        const int r0 = bm0 + wm + mi * 16 + ar;
        const int r1 = r0 + 8;
        float s0 = 1.f, s1 = 1.f;
        if (SCALE) {
            s0 = 1.f + strength * (gains[r0] - 1.f);
            s1 = 1.f + strength * (gains[r1] - 1.f);
        }
        #pragma unroll
        for (int ni = 0; ni < 8; ni++) {
            const int col = bn0 + wn + ni * 8 + ac * 2;
            const float b0 = bias[col], b1 = bias[col + 1];
            float2 o0, o1;
            o0.x = (acc[mi][ni][0] + b0) * s0;
            o0.y = (acc[mi][ni][1] + b1) * s0;
            o1.x = (acc[mi][ni][2] + b0) * s1;
            o1.y = (acc[mi][ni][3] + b1) * s1;
            *(float2*)&C[(size_t)r0 * N + col] = o0;
            *(float2*)&C[(size_t)r1 * N + col] = o1;
        }
    }
}

// ---------------------------------------------------------------------------
// GIF scan: cur (f32, in) -> spikes (fp16, out); sequential over S per channel
// ---------------------------------------------------------------------------
__global__ void gif_scan(const float* __restrict__ cur, __half* __restrict__ spk, int D)
{
    const int t = blockIdx.x * blockDim.x + threadIdx.x;
    if (t >= B_ * D) return;
    const int b = t / D, d = t % D;
    const float* p = cur + (size_t)b * S_ * D + d;
    __half* q = spk + (size_t)b * S_ * D + d;

    const float KX = 4.0f * 1.4426950408889634f;  // 4*log2(e)
    float v = 0.f;
    #pragma unroll 1
    for (int s0 = 0; s0 < S_; s0 += 8) {
        float c[8];
        #pragma unroll
        for (int i = 0; i < 8; i++) c[i] = p[(size_t)(s0 + i) * D];
        #pragma unroll
        for (int i = 0; i < 8; i++) {
            v = fmaf(DECAY, v, c[i]);
            const float e  = fast_ex2(fmaf(-KX, v, KX));   // exp(-4(v-1))
            const float sp = fast_rcp(1.0f + e);
            q[(size_t)(s0 + i) * D] = __float2half_rn(sp);
            v -= sp;
        }
    }
}

// ---------------------------------------------------------------------------
// launch
// ---------------------------------------------------------------------------
extern "C" void kernel_launch(void* const* d_in, const int* in_sizes, int n_in,
                              void* d_out, int out_size)
{
    const void*  ids   = d_in[0];
    const float* gains = (const float*)d_in[1];
    const float* emb   = (const float*)d_in[2];
    const float* encW  = (const float*)d_in[3];
    const float* encb  = (const float*)d_in[4];
    const float* decW  = (const float*)d_in[5];
    const float* decb  = (const float*)d_in[6];
    const float* outW  = (const float*)d_in[7];
    const float* outb  = (const float*)d_in[8];
    float* out = (float*)d_out;

    float  *buf1, *buf2;
    __half *s1h, *s2h, *embH, *encWt, *decWt, *outWt;
    cudaGetSymbolAddress((void**)&buf1,  g_buf1);
    cudaGetSymbolAddress((void**)&buf2,  g_buf2);
    cudaGetSymbolAddress((void**)&s1h,   g_s1h);
    cudaGetSymbolAddress((void**)&s2h,   g_s2h);
    cudaGetSymbolAddress((void**)&embH,  g_embH);
    cudaGetSymbolAddress((void**)&encWt, g_encWt);
    cudaGetSymbolAddress((void**)&decWt, g_decWt);
    cudaGetSymbolAddress((void**)&outWt, g_outWt);

    cudaFuncSetAttribute(gemm_h<true>,  cudaFuncAttributeMaxDynamicSharedMemorySize, SMEM_BYTES);
    cudaFuncSetAttribute(gemm_h<false>, cudaFuncAttributeMaxDynamicSharedMemorySize, SMEM_BYTES);

    sniff_ids<<<1, 32>>>((const int*)ids);

    // fp16 operand prep
    gather_h<<<M_, 256>>>(emb, ids, embH);
    conv_transpose<<<dim3(H_/64, E_/64), 256>>>(encW, encWt, E_, H_);
    conv_transpose<<<dim3(E_/64, H_/64), 256>>>(decW, decWt, H_, E_);
    conv_transpose<<<dim3(V_/64, E_/64), 256>>>(outW, outWt, E_, V_);

    // enc: cur1 = (embH @ encW + encb) * (1+0.3*(g-1))    [4096 x 2048, K=1024]
    gemm_h<true><<<dim3(M_/PBM, H_/PBN), 256, SMEM_BYTES>>>(
        embH, encWt, encb, gains, 0.3f, buf1, M_, H_, E_);
    gif_scan<<<(B_*H_ + 127) / 128, 128>>>(buf1, s1h, H_);

    // dec: cur2 = (spikes1 @ decW + decb) * (1+0.2*(g-1)) [4096 x 1024, K=2048]
    gemm_h<true><<<dim3(M_/PBM, E_/PBN), 256, SMEM_BYTES>>>(
        s1h, decWt, decb, gains, 0.2f, buf2, M_, E_, H_);
    gif_scan<<<(B_*E_ + 127) / 128, 128>>>(buf2, s2h, E_);

    // out: logits = spikes2 @ outW + outb                 [4096 x 32000, K=1024]
    gemm_h<false><<<dim3(M_/PBM, V_/PBN), 256, SMEM_BYTES>>>(
        s2h, outWt, outb, nullptr, 0.f, out, M_, V_, E_);
}

// round 8
// speedup vs baseline: 1.6564x; 1.0038x over previous
#include <cuda_runtime.h>
#include <cuda_fp16.h>
#include <cstdint>
#include <cstddef>

#define DECAY 0.9f

#define B_ 2
#define S_ 2048
#define V_ 32000
#define E_ 1024
#define H_ 2048
#define M_ (B_*S_)   // 4096 rows

// Scratch (allocation-free rule: device globals)
__device__ float  g_buf1[(size_t)M_ * H_];    // 32 MB: cur1 (f32)
__device__ float  g_buf2[(size_t)M_ * E_];    // 16 MB: cur2 (f32)
__device__ __half g_s1h [(size_t)M_ * H_];    // 16 MB: spikes1 (fp16)
__device__ __half g_s2h [(size_t)M_ * E_];    //  8 MB: spikes2 (fp16)
__device__ __half g_embH[(size_t)M_ * E_];    //  8 MB: gathered embeddings (fp16)
__device__ __half g_encWt[(size_t)H_ * E_];   //  4 MB: enc_W^T  [H][E]
__device__ __half g_decWt[(size_t)E_ * H_];   //  4 MB: dec_W^T  [E][H]
__device__ __half g_outWt[(size_t)V_ * E_];   // 64 MB: out_W^T  [V][E]
__device__ int    g_ids_is64;

// ---------------------------------------------------------------------------
// helpers
// ---------------------------------------------------------------------------
__device__ __forceinline__ float fast_ex2(float x) {
    float y; asm("ex2.approx.f32 %0, %1;" : "=f"(y) : "f"(x)); return y;
}
__device__ __forceinline__ float fast_rcp(float x) {
    float y; asm("rcp.approx.f32 %0, %1;" : "=f"(y) : "f"(x)); return y;
}
__device__ __forceinline__ void mma16(float* c, const unsigned* a, const unsigned* b) {
    asm volatile(
        "mma.sync.aligned.m16n8k16.row.col.f32.f16.f16.f32 "
        "{%0,%1,%2,%3}, {%4,%5,%6,%7}, {%8,%9}, {%0,%1,%2,%3};\n"
        : "+f"(c[0]), "+f"(c[1]), "+f"(c[2]), "+f"(c[3])
        : "r"(a[0]), "r"(a[1]), "r"(a[2]), "r"(a[3]), "r"(b[0]), "r"(b[1]));
}
__device__ __forceinline__ void ldsm4(unsigned& r0, unsigned& r1, unsigned& r2,
                                      unsigned& r3, uint32_t a) {
    asm volatile("ldmatrix.sync.aligned.m8n8.x4.shared.b16 {%0,%1,%2,%3}, [%4];"
                 : "=r"(r0), "=r"(r1), "=r"(r2), "=r"(r3) : "r"(a));
}
__device__ __forceinline__ uint32_t smem_u32(const void* p) {
    uint32_t a;
    asm("{ .reg .u64 t; cvta.to.shared.u64 t, %1; cvt.u32.u64 %0, t; }" : "=r"(a) : "l"(p));
    return a;
}
__device__ __forceinline__ void cp16(uint32_t s, const void* g) {
    asm volatile("cp.async.cg.shared.global [%0], [%1], 16;" :: "r"(s), "l"(g) : "memory");
}
__device__ __forceinline__ void cp_commit() {
    asm volatile("cp.async.commit_group;" ::: "memory");
}
template<int N>
__device__ __forceinline__ void cp_wait() {
    asm volatile("cp.async.wait_group %0;" :: "n"(N) : "memory");
}

// ---------------------------------------------------------------------------
// dtype sniffer for input_ids (int32 vs int64)
// ---------------------------------------------------------------------------
__global__ void sniff_ids(const int* __restrict__ ids32) {
    if (threadIdx.x == 0 && blockIdx.x == 0) {
        int zeros = 0;
        for (int i = 1; i < 255; i += 2) zeros += (ids32[i] == 0);
        g_ids_is64 = (zeros > 64) ? 1 : 0;
    }
}

// ---------------------------------------------------------------------------
// weight transpose + fp32->fp16:  W[K][N] -> Wt[N][K]
// 64x64 tile, 256 threads. float4 gmem loads, 16B half stores (coalesced).
// Requires K%64==0, N%64==0.
// ---------------------------------------------------------------------------
__global__ void conv_transpose(const float* __restrict__ W, __half* __restrict__ Wt,
                               int K, int N)
{
    __shared__ float ts[64][65];
    const int k0 = blockIdx.y * 64, n0 = blockIdx.x * 64;
    const int t  = threadIdx.x;

    // load: thread -> k rows t>>4 (+16 step), n cols (t&15)*4
    const int lk = t >> 4, ln = (t & 15) * 4;
    #pragma unroll
    for (int i = 0; i < 4; i++) {
        float4 v = *(const float4*)&W[(size_t)(k0 + lk + 16 * i) * N + n0 + ln];
        ts[lk + 16 * i][ln]     = v.x;
        ts[lk + 16 * i][ln + 1] = v.y;
        ts[lk + 16 * i][ln + 2] = v.z;
        ts[lk + 16 * i][ln + 3] = v.w;
    }
    __syncthreads();

    // store: thread -> n row t>>2, k chunk (t&3)*16; 2x 16B stores
    const int sn = t >> 2, sk = (t & 3) * 16;
    uint4 o[2];
    __half2* oh = (__half2*)o;
    #pragma unroll
    for (int j = 0; j < 8; j++)
        oh[j] = __floats2half2_rn(ts[sk + 2*j][sn], ts[sk + 2*j + 1][sn]);
    uint4* dst = (uint4*)&Wt[(size_t)(n0 + sn) * K + k0 + sk];
    dst[0] = o[0];
    dst[1] = o[1];
}

// ---------------------------------------------------------------------------
// embedding gather -> fp16
// ---------------------------------------------------------------------------
__global__ void gather_h(const float* __restrict__ emb, const void* __restrict__ idsv,
                         __half* __restrict__ dst)
{
    const int row = blockIdx.x;
    long long id = g_ids_is64 ? ((const long long*)idsv)[row]
                              : (long long)((const int*)idsv)[row];
    const float4* s = (const float4*)(emb + (size_t)id * E_);
    __half2* d = (__half2*)(dst + (size_t)row * E_);
    const int c = threadIdx.x;            // 256 threads, E/4 = 256 float4
    float4 v = s[c];
    d[2*c]   = __floats2half2_rn(v.x, v.y);
    d[2*c+1] = __floats2half2_rn(v.z, v.w);
}

// ---------------------------------------------------------------------------
// fp16 NT GEMM:  C[M,N](f32) = (A[M,K](h) @ Wt[N,K](h)^T + bias) * rowscale
// Block 128x256x32, 5-stage cp.async, 8 warps (2m x 4n), warp 64x64,
// mma.m16n8k16 with ldmatrix.x4 fragment loads.
// SMEM rows: pitch 40 halfs (80B) => LDSM conflict-free.
// Requires M%128==0, N%256==0, K%32==0.
// ---------------------------------------------------------------------------
#define PBM 128
#define PBN 256
#define PBK 32
#define STAGES 5
#define ROW_B 80                              // bytes per smem row (40 halfs)
#define A_BYTES (PBM * ROW_B)                 // 10240
#define B_BYTES (PBN * ROW_B)                 // 20480
#define STG_B (A_BYTES + B_BYTES)             // 30720
#define SMEM_BYTES (STAGES * STG_B)           // 153600

template<bool SCALE>
__global__ void __launch_bounds__(256, 1)
gemm_h(const __half* __restrict__ A, const __half* __restrict__ Wt,
       const float* __restrict__ bias, const float* __restrict__ gains,
       float strength, float* __restrict__ C, int M, int N, int K)
{
    extern __shared__ __align__(16) char sm[];
    const uint32_t sbase = smem_u32(sm);

    const int tid = threadIdx.x;
    const int bm0 = blockIdx.x * PBM;
    const int bn0 = blockIdx.y * PBN;

    // ---- copy mapping: 4 threads per row, 16B chunks along K ----
    const int crow  = tid >> 2;               // 0..63
    const int cchk  = tid & 3;                // 16B chunk in row
    const __half* ag = A  + (size_t)(bm0 + crow) * K + cchk * 8;
    const __half* bg = Wt + (size_t)(bn0 + crow) * K + cchk * 8;
    const size_t rowStep = (size_t)64 * K;

    const int niter = K / PBK;

    auto issue = [&](int stage, int k0) {
        const uint32_t sa = sbase + stage * STG_B;
        #pragma unroll
        for (int j = 0; j < 2; j++)            // A: 128 rows
            cp16(sa + (crow + 64 * j) * ROW_B + cchk * 16,
                 ag + (size_t)j * rowStep + k0);
        const uint32_t sb = sa + A_BYTES;
        #pragma unroll
        for (int j = 0; j < 4; j++)            // B: 256 rows
            cp16(sb + (crow + 64 * j) * ROW_B + cchk * 16,
                 bg + (size_t)j * rowStep + k0);
    };

    // ---- mma mapping: 8 warps 2m x 4n, warp tile 64x64 ----
    const int lane = tid & 31;
    const int wid  = tid >> 5;
    const int wm   = (wid & 1) * 64;
    const int wn   = (wid >> 1) * 64;
    const int ar   = lane >> 2;                // 0..7
    const int ac   = lane & 3;                 // 0..3

    // ldmatrix lane address offsets (within a stage)
    // A frag mi: m0=rows0-7 klo, m1=rows8-15 klo, m2=rows0-7 khi, m3=rows8-15 khi
    const int a_row16 = ((lane >> 3) & 1) * 8 + (lane & 7);
    const int a_koff  = (lane >> 4) * 8;              // halfs
    uint32_t aoff[4];
    #pragma unroll
    for (int mi = 0; mi < 4; mi++)
        aoff[mi] = (uint32_t)(wm + mi * 16 + a_row16) * ROW_B + a_koff * 2;
    // B frag pair p (ni=2p,2p+1): m0=rows(2p*8) klo, m1=rows(2p*8) khi,
    //                             m2=rows((2p+1)*8) klo, m3=khi
    const int b_rowsel = ((lane >> 4) & 1) * 8 + (lane & 7);
    const int b_koff   = ((lane >> 3) & 1) * 8;       // halfs
    uint32_t boff[4];
    #pragma unroll
    for (int p = 0; p < 4; p++)
        boff[p] = A_BYTES + (uint32_t)(wn + p * 16 + b_rowsel) * ROW_B + b_koff * 2;

    float acc[4][8][4];
    #pragma unroll
    for (int mi = 0; mi < 4; mi++)
        #pragma unroll
        for (int ni = 0; ni < 8; ni++)
            #pragma unroll
            for (int j = 0; j < 4; j++) acc[mi][ni][j] = 0.f;

    #pragma unroll
    for (int s = 0; s < STAGES - 1; s++) {
        if (s < niter) issue(s, s * PBK);
        cp_commit();
    }

    for (int kt = 0; kt < niter; kt++) {
        cp_wait<STAGES - 2>();
        __syncthreads();

        const int nk = kt + STAGES - 1;
        if (nk < niter) issue(nk % STAGES, nk * PBK);
        cp_commit();

        const uint32_t stb = sbase + (uint32_t)(kt % STAGES) * STG_B;

        #pragma unroll
        for (int ks = 0; ks < PBK; ks += 16) {
            const uint32_t kb = ks * 2;        // byte offset along K
            unsigned a[4][4], b[8][2];
            #pragma unroll
            for (int mi = 0; mi < 4; mi++)
                ldsm4(a[mi][0], a[mi][1], a[mi][2], a[mi][3], stb + aoff[mi] + kb);
            #pragma unroll
            for (int p = 0; p < 4; p++)
                ldsm4(b[2*p][0], b[2*p][1], b[2*p+1][0], b[2*p+1][1],
                      stb + boff[p] + kb);
            #pragma unroll
            for (int mi = 0; mi < 4; mi++)
                #pragma unroll
                for (int ni = 0; ni < 8; ni++)
                    mma16(acc[mi][ni], a[mi], b[ni]);
        }
    }

    // ---- epilogue: bias + optional row scale ----
    #pragma unroll
    for (int mi = 0; mi < 4; mi++) {
        const int r0 = bm0 + wm + mi * 16 + ar;
        const int r1 = r0 + 8;
        float s0 = 1.f, s1 = 1.f;
        if (SCALE) {
            s0 = 1.f + strength * (gains[r0] - 1.f);
            s1 = 1.f + strength * (gains[r1] - 1.f);
        }
        #pragma unroll
        for (int ni = 0; ni < 8; ni++) {
            const int col = bn0 + wn + ni * 8 + ac * 2;
            const float b0 = bias[col], b1 = bias[col + 1];
            float2 o0, o1;
            o0.x = (acc[mi][ni][0] + b0) * s0;
            o0.y = (acc[mi][ni][1] + b1) * s0;
            o1.x = (acc[mi][ni][2] + b0) * s1;
            o1.y = (acc[mi][ni][3] + b1) * s1;
            *(float2*)&C[(size_t)r0 * N + col] = o0;
            *(float2*)&C[(size_t)r1 * N + col] = o1;
        }
    }
}

// ---------------------------------------------------------------------------
// GIF scan: cur (f32, in) -> spikes (fp16, out); sequential over S per channel
// ---------------------------------------------------------------------------
__global__ void gif_scan(const float* __restrict__ cur, __half* __restrict__ spk, int D)
{
    const int t = blockIdx.x * blockDim.x + threadIdx.x;
    if (t >= B_ * D) return;
    const int b = t / D, d = t % D;
    const float* p = cur + (size_t)b * S_ * D + d;
    __half* q = spk + (size_t)b * S_ * D + d;

    const float KX = 4.0f * 1.4426950408889634f;  // 4*log2(e)
    float v = 0.f;
    #pragma unroll 1
    for (int s0 = 0; s0 < S_; s0 += 8) {
        float c[8];
        #pragma unroll
        for (int i = 0; i < 8; i++) c[i] = p[(size_t)(s0 + i) * D];
        #pragma unroll
        for (int i = 0; i < 8; i++) {
            v = fmaf(DECAY, v, c[i]);
            const float e  = fast_ex2(fmaf(-KX, v, KX));   // exp(-4(v-1))
            const float sp = fast_rcp(1.0f + e);
            q[(size_t)(s0 + i) * D] = __float2half_rn(sp);
            v -= sp;
        }
    }
}

// ---------------------------------------------------------------------------
// launch
// ---------------------------------------------------------------------------
extern "C" void kernel_launch(void* const* d_in, const int* in_sizes, int n_in,
                              void* d_out, int out_size)
{
    const void*  ids   = d_in[0];
    const float* gains = (const float*)d_in[1];
    const float* emb   = (const float*)d_in[2];
    const float* encW  = (const float*)d_in[3];
    const float* encb  = (const float*)d_in[4];
    const float* decW  = (const float*)d_in[5];
    const float* decb  = (const float*)d_in[6];
    const float* outW  = (const float*)d_in[7];
    const float* outb  = (const float*)d_in[8];
    float* out = (float*)d_out;

    float  *buf1, *buf2;
    __half *s1h, *s2h, *embH, *encWt, *decWt, *outWt;
    cudaGetSymbolAddress((void**)&buf1,  g_buf1);
    cudaGetSymbolAddress((void**)&buf2,  g_buf2);
    cudaGetSymbolAddress((void**)&s1h,   g_s1h);
    cudaGetSymbolAddress((void**)&s2h,   g_s2h);
    cudaGetSymbolAddress((void**)&embH,  g_embH);
    cudaGetSymbolAddress((void**)&encWt, g_encWt);
    cudaGetSymbolAddress((void**)&decWt, g_decWt);
    cudaGetSymbolAddress((void**)&outWt, g_outWt);

    cudaFuncSetAttribute(gemm_h<true>,  cudaFuncAttributeMaxDynamicSharedMemorySize, SMEM_BYTES);
    cudaFuncSetAttribute(gemm_h<false>, cudaFuncAttributeMaxDynamicSharedMemorySize, SMEM_BYTES);

    sniff_ids<<<1, 32>>>((const int*)ids);

    // fp16 operand prep
    gather_h<<<M_, 256>>>(emb, ids, embH);
    conv_transpose<<<dim3(H_/64, E_/64), 256>>>(encW, encWt, E_, H_);
    conv_transpose<<<dim3(E_/64, H_/64), 256>>>(decW, decWt, H_, E_);
    conv_transpose<<<dim3(V_/64, E_/64), 256>>>(outW, outWt, E_, V_);

    // enc: cur1 = (embH @ encW + encb) * (1+0.3*(g-1))    [4096 x 2048, K=1024]
    gemm_h<true><<<dim3(M_/PBM, H_/PBN), 256, SMEM_BYTES>>>(
        embH, encWt, encb, gains, 0.3f, buf1, M_, H_, E_);
    gif_scan<<<(B_*H_ + 127) / 128, 128>>>(buf1, s1h, H_);

    // dec: cur2 = (spikes1 @ decW + decb) * (1+0.2*(g-1)) [4096 x 1024, K=2048]
    gemm_h<true><<<dim3(M_/PBM, E_/PBN), 256, SMEM_BYTES>>>(
        s1h, decWt, decb, gains, 0.2f, buf2, M_, E_, H_);
    gif_scan<<<(B_*E_ + 127) / 128, 128>>>(buf2, s2h, E_);

    // out: logits = spikes2 @ outW + outb                 [4096 x 32000, K=1024]
    gemm_h<false><<<dim3(M_/PBM, V_/PBN), 256, SMEM_BYTES>>>(
        s2h, outWt, outb, nullptr, 0.f, out, M_, V_, E_);
}

// round 9
// speedup vs baseline: 1.6853x; 1.0175x over previous
#include <cuda_runtime.h>
#include <cuda_fp16.h>
#include <cstdint>
#include <cstddef>

#define DECAY 0.9f

#define B_ 2
#define S_ 2048
#define V_ 32000
#define E_ 1024
#define H_ 2048
#define M_ (B_*S_)   // 4096 rows

// Scratch (allocation-free rule: device globals)
__device__ float  g_buf1[(size_t)M_ * H_];    // 32 MB: cur1 (f32)
__device__ float  g_buf2[(size_t)M_ * E_];    // 16 MB: cur2 (f32)
__device__ __half g_s1h [(size_t)M_ * H_];    // 16 MB: spikes1 (fp16)
__device__ __half g_s2h [(size_t)M_ * E_];    //  8 MB: spikes2 (fp16)
__device__ __half g_embH[(size_t)M_ * E_];    //  8 MB: gathered embeddings (fp16)
__device__ __half g_encWt[(size_t)H_ * E_];   //  4 MB: enc_W^T  [H][E]
__device__ __half g_decWt[(size_t)E_ * H_];   //  4 MB: dec_W^T  [E][H]
__device__ __half g_outWt[(size_t)V_ * E_];   // 64 MB: out_W^T  [V][E]
__device__ int    g_ids_is64;

// ---------------------------------------------------------------------------
// helpers
// ---------------------------------------------------------------------------
__device__ __forceinline__ float fast_ex2(float x) {
    float y; asm("ex2.approx.f32 %0, %1;" : "=f"(y) : "f"(x)); return y;
}
__device__ __forceinline__ float fast_rcp(float x) {
    float y; asm("rcp.approx.f32 %0, %1;" : "=f"(y) : "f"(x)); return y;
}
__device__ __forceinline__ void mma16(float* c, const unsigned* a, const unsigned* b) {
    asm volatile(
        "mma.sync.aligned.m16n8k16.row.col.f32.f16.f16.f32 "
        "{%0,%1,%2,%3}, {%4,%5,%6,%7}, {%8,%9}, {%0,%1,%2,%3};\n"
        : "+f"(c[0]), "+f"(c[1]), "+f"(c[2]), "+f"(c[3])
        : "r"(a[0]), "r"(a[1]), "r"(a[2]), "r"(a[3]), "r"(b[0]), "r"(b[1]));
}
__device__ __forceinline__ void ldsm4(unsigned& r0, unsigned& r1, unsigned& r2,
                                      unsigned& r3, uint32_t a) {
    asm volatile("ldmatrix.sync.aligned.m8n8.x4.shared.b16 {%0,%1,%2,%3}, [%4];"
                 : "=r"(r0), "=r"(r1), "=r"(r2), "=r"(r3) : "r"(a));
}
__device__ __forceinline__ uint32_t smem_u32(const void* p) {
    uint32_t a;
    asm("{ .reg .u64 t; cvta.to.shared.u64 t, %1; cvt.u32.u64 %0, t; }" : "=r"(a) : "l"(p));
    return a;
}
__device__ __forceinline__ void cp16(uint32_t s, const void* g) {
    asm volatile("cp.async.cg.shared.global [%0], [%1], 16;" :: "r"(s), "l"(g) : "memory");
}
__device__ __forceinline__ void cp_commit() {
    asm volatile("cp.async.commit_group;" ::: "memory");
}
template<int N>
__device__ __forceinline__ void cp_wait() {
    asm volatile("cp.async.wait_group %0;" :: "n"(N) : "memory");
}

// ---------------------------------------------------------------------------
// dtype sniffer for input_ids (int32 vs int64)
// ---------------------------------------------------------------------------
__global__ void sniff_ids(const int* __restrict__ ids32) {
    if (threadIdx.x == 0 && blockIdx.x == 0) {
        int zeros = 0;
        for (int i = 1; i < 255; i += 2) zeros += (ids32[i] == 0);
        g_ids_is64 = (zeros > 64) ? 1 : 0;
    }
}

// ---------------------------------------------------------------------------
// weight transpose + fp32->fp16:  W[K][N] -> Wt[N][K]
// ---------------------------------------------------------------------------
__global__ void conv_transpose(const float* __restrict__ W, __half* __restrict__ Wt,
                               int K, int N)
{
    __shared__ float ts[64][65];
    const int k0 = blockIdx.y * 64, n0 = blockIdx.x * 64;
    const int t  = threadIdx.x;

    const int lk = t >> 4, ln = (t & 15) * 4;
    #pragma unroll
    for (int i = 0; i < 4; i++) {
        float4 v = *(const float4*)&W[(size_t)(k0 + lk + 16 * i) * N + n0 + ln];
        ts[lk + 16 * i][ln]     = v.x;
        ts[lk + 16 * i][ln + 1] = v.y;
        ts[lk + 16 * i][ln + 2] = v.z;
        ts[lk + 16 * i][ln + 3] = v.w;
    }
    __syncthreads();

    const int sn = t >> 2, sk = (t & 3) * 16;
    uint4 o[2];
    __half2* oh = (__half2*)o;
    #pragma unroll
    for (int j = 0; j < 8; j++)
        oh[j] = __floats2half2_rn(ts[sk + 2*j][sn], ts[sk + 2*j + 1][sn]);
    uint4* dst = (uint4*)&Wt[(size_t)(n0 + sn) * K + k0 + sk];
    dst[0] = o[0];
    dst[1] = o[1];
}

// ---------------------------------------------------------------------------
// embedding gather -> fp16
// ---------------------------------------------------------------------------
__global__ void gather_h(const float* __restrict__ emb, const void* __restrict__ idsv,
                         __half* __restrict__ dst)
{
    const int row = blockIdx.x;
    long long id = g_ids_is64 ? ((const long long*)idsv)[row]
                              : (long long)((const int*)idsv)[row];
    const float4* s = (const float4*)(emb + (size_t)id * E_);
    __half2* d = (__half2*)(dst + (size_t)row * E_);
    const int c = threadIdx.x;            // 256 threads, E/4 = 256 float4
    float4 v = s[c];
    d[2*c]   = __floats2half2_rn(v.x, v.y);
    d[2*c+1] = __floats2half2_rn(v.z, v.w);
}

// ---------------------------------------------------------------------------
// fp16 NT GEMM:  C[M,N](f32) = (A[M,K](h) @ Wt[N,K](h)^T + bias) * rowscale
// Block 128x256x32, 5-stage cp.async, 512 threads / 16 warps (2m x 8n),
// warp tile 64x32, mma.m16n8k16 with ldmatrix.x4.
// SMEM rows pitch 40 halfs (80B) => LDSM conflict-free.
// ---------------------------------------------------------------------------
#define PBM 128
#define PBN 256
#define PBK 32
#define STAGES 5
#define ROW_B 80                              // bytes per smem row (40 halfs)
#define A_BYTES (PBM * ROW_B)                 // 10240
#define B_BYTES (PBN * ROW_B)                 // 20480
#define STG_B (A_BYTES + B_BYTES)             // 30720
#define SMEM_BYTES (STAGES * STG_B)           // 153600

template<bool SCALE>
__global__ void __launch_bounds__(512, 1)
gemm_h(const __half* __restrict__ A, const __half* __restrict__ Wt,
       const float* __restrict__ bias, const float* __restrict__ gains,
       float strength, float* __restrict__ C, int M, int N, int K)
{
    extern __shared__ __align__(16) char sm[];
    const uint32_t sbase = smem_u32(sm);

    const int tid = threadIdx.x;
    const int bm0 = blockIdx.x * PBM;
    const int bn0 = blockIdx.y * PBN;

    // ---- copy mapping: 4 threads per row (16B chunks along K), 512 threads ----
    const int crow = tid >> 2;                // 0..127
    const int cchk = tid & 3;
    const __half* ag = A  + (size_t)(bm0 + crow) * K + cchk * 8;
    const __half* bg = Wt + (size_t)(bn0 + crow) * K + cchk * 8;
    const size_t rowStep = (size_t)128 * K;

    const int niter = K / PBK;

    auto issue = [&](int stage, int k0) {
        const uint32_t sa = sbase + stage * STG_B;
        cp16(sa + crow * ROW_B + cchk * 16, ag + k0);            // A: 128 rows
        const uint32_t sb = sa + A_BYTES;
        #pragma unroll
        for (int j = 0; j < 2; j++)                               // B: 256 rows
            cp16(sb + (crow + 128 * j) * ROW_B + cchk * 16,
                 bg + (size_t)j * rowStep + k0);
    };

    // ---- mma mapping: 16 warps 2m x 8n, warp tile 64x32 ----
    const int lane = tid & 31;
    const int wid  = tid >> 5;
    const int wm   = (wid & 1) * 64;
    const int wn   = (wid >> 1) * 32;
    const int ar   = lane >> 2;                // 0..7
    const int ac   = lane & 3;                 // 0..3

    // ldmatrix lane address offsets (within a stage)
    const int a_row16 = ((lane >> 3) & 1) * 8 + (lane & 7);
    const int a_koff  = (lane >> 4) * 8;              // halfs
    uint32_t aoff[4];
    #pragma unroll
    for (int mi = 0; mi < 4; mi++)
        aoff[mi] = (uint32_t)(wm + mi * 16 + a_row16) * ROW_B + a_koff * 2;
    const int b_rowsel = ((lane >> 4) & 1) * 8 + (lane & 7);
    const int b_koff   = ((lane >> 3) & 1) * 8;       // halfs
    uint32_t boff[2];
    #pragma unroll
    for (int p = 0; p < 2; p++)
        boff[p] = A_BYTES + (uint32_t)(wn + p * 16 + b_rowsel) * ROW_B + b_koff * 2;

    float acc[4][4][4];
    #pragma unroll
    for (int mi = 0; mi < 4; mi++)
        #pragma unroll
        for (int ni = 0; ni < 4; ni++)
            #pragma unroll
            for (int j = 0; j < 4; j++) acc[mi][ni][j] = 0.f;

    #pragma unroll
    for (int s = 0; s < STAGES - 1; s++) {
        if (s < niter) issue(s, s * PBK);
        cp_commit();
    }

    for (int kt = 0; kt < niter; kt++) {
        cp_wait<STAGES - 2>();
        __syncthreads();

        const int nk = kt + STAGES - 1;
        if (nk < niter) issue(nk % STAGES, nk * PBK);
        cp_commit();

        const uint32_t stb = sbase + (uint32_t)(kt % STAGES) * STG_B;

        #pragma unroll
        for (int ks = 0; ks < PBK; ks += 16) {
            const uint32_t kb = ks * 2;        // byte offset along K
            unsigned a[4][4], b[4][2];
            #pragma unroll
            for (int mi = 0; mi < 4; mi++)
                ldsm4(a[mi][0], a[mi][1], a[mi][2], a[mi][3], stb + aoff[mi] + kb);
            #pragma unroll
            for (int p = 0; p < 2; p++)
                ldsm4(b[2*p][0], b[2*p][1], b[2*p+1][0], b[2*p+1][1],
                      stb + boff[p] + kb);
            #pragma unroll
            for (int mi = 0; mi < 4; mi++)
                #pragma unroll
                for (int ni = 0; ni < 4; ni++)
                    mma16(acc[mi][ni], a[mi], b[ni]);
        }
    }

    // ---- epilogue: bias + optional row scale ----
    #pragma unroll
    for (int mi = 0; mi < 4; mi++) {
        const int r0 = bm0 + wm + mi * 16 + ar;
        const int r1 = r0 + 8;
        float s0 = 1.f, s1 = 1.f;
        if (SCALE) {
            s0 = 1.f + strength * (gains[r0] - 1.f);
            s1 = 1.f + strength * (gains[r1] - 1.f);
        }
        #pragma unroll
        for (int ni = 0; ni < 4; ni++) {
            const int col = bn0 + wn + ni * 8 + ac * 2;
            const float b0 = bias[col], b1 = bias[col + 1];
            float2 o0, o1;
            o0.x = (acc[mi][ni][0] + b0) * s0;
            o0.y = (acc[mi][ni][1] + b1) * s0;
            o1.x = (acc[mi][ni][2] + b0) * s1;
            o1.y = (acc[mi][ni][3] + b1) * s1;
            *(float2*)&C[(size_t)r0 * N + col] = o0;
            *(float2*)&C[(size_t)r1 * N + col] = o1;
        }
    }
}

// ---------------------------------------------------------------------------
// GIF scan: cur (f32) -> spikes (fp16); sequential over S per channel.
// 16-wide groups, double-buffered prefetch: loads of group i+1 overlap the
// 16-step serial compute of group i (only 2B/4K channels exist, so ILP is
// the only latency lever).
// ---------------------------------------------------------------------------
__global__ void gif_scan(const float* __restrict__ cur, __half* __restrict__ spk, int D)
{
    const int t = blockIdx.x * blockDim.x + threadIdx.x;
    if (t >= B_ * D) return;
    const int b = t / D, d = t % D;
    const float* p = cur + (size_t)b * S_ * D + d;
    __half* q = spk + (size_t)b * S_ * D + d;

    const float KX = 4.0f * 1.4426950408889634f;  // 4*log2(e)
    float c[2][16];
    #pragma unroll
    for (int i = 0; i < 16; i++) c[0][i] = p[(size_t)i * D];

    float v = 0.f;
    #pragma unroll 1
    for (int s0 = 0; s0 < S_; s0 += 16) {
        const int buf = (s0 >> 4) & 1;
        if (s0 + 16 < S_) {
            #pragma unroll
            for (int i = 0; i < 16; i++)
                c[buf ^ 1][i] = p[(size_t)(s0 + 16 + i) * D];
        }
        #pragma unroll
        for (int i = 0; i < 16; i++) {
            v = fmaf(DECAY, v, c[buf][i]);
            const float e  = fast_ex2(fmaf(-KX, v, KX));   // exp(-4(v-1))
            const float sp = fast_rcp(1.0f + e);
            q[(size_t)(s0 + i) * D] = __float2half_rn(sp);
            v -= sp;
        }
    }
}

// ---------------------------------------------------------------------------
// launch
// ---------------------------------------------------------------------------
extern "C" void kernel_launch(void* const* d_in, const int* in_sizes, int n_in,
                              void* d_out, int out_size)
{
    const void*  ids   = d_in[0];
    const float* gains = (const float*)d_in[1];
    const float* emb   = (const float*)d_in[2];
    const float* encW  = (const float*)d_in[3];
    const float* encb  = (const float*)d_in[4];
    const float* decW  = (const float*)d_in[5];
    const float* decb  = (const float*)d_in[6];
    const float* outW  = (const float*)d_in[7];
    const float* outb  = (const float*)d_in[8];
    float* out = (float*)d_out;

    float  *buf1, *buf2;
    __half *s1h, *s2h, *embH, *encWt, *decWt, *outWt;
    cudaGetSymbolAddress((void**)&buf1,  g_buf1);
    cudaGetSymbolAddress((void**)&buf2,  g_buf2);
    cudaGetSymbolAddress((void**)&s1h,   g_s1h);
    cudaGetSymbolAddress((void**)&s2h,   g_s2h);
    cudaGetSymbolAddress((void**)&embH,  g_embH);
    cudaGetSymbolAddress((void**)&encWt, g_encWt);
    cudaGetSymbolAddress((void**)&decWt, g_decWt);
    cudaGetSymbolAddress((void**)&outWt, g_outWt);

    cudaFuncSetAttribute(gemm_h<true>,  cudaFuncAttributeMaxDynamicSharedMemorySize, SMEM_BYTES);
    cudaFuncSetAttribute(gemm_h<false>, cudaFuncAttributeMaxDynamicSharedMemorySize, SMEM_BYTES);

    sniff_ids<<<1, 32>>>((const int*)ids);

    // fp16 operand prep
    gather_h<<<M_, 256>>>(emb, ids, embH);
    conv_transpose<<<dim3(H_/64, E_/64), 256>>>(encW, encWt, E_, H_);
    conv_transpose<<<dim3(E_/64, H_/64), 256>>>(decW, decWt, H_, E_);
    conv_transpose<<<dim3(V_/64, E_/64), 256>>>(outW, outWt, E_, V_);

    // enc: cur1 = (embH @ encW + encb) * (1+0.3*(g-1))    [4096 x 2048, K=1024]
    gemm_h<true><<<dim3(M_/PBM, H_/PBN), 512, SMEM_BYTES>>>(
        embH, encWt, encb, gains, 0.3f, buf1, M_, H_, E_);
    gif_scan<<<(B_*H_ + 127) / 128, 128>>>(buf1, s1h, H_);

    // dec: cur2 = (spikes1 @ decW + decb) * (1+0.2*(g-1)) [4096 x 1024, K=2048]
    gemm_h<true><<<dim3(M_/PBM, E_/PBN), 512, SMEM_BYTES>>>(
        s1h, decWt, decb, gains, 0.2f, buf2, M_, E_, H_);
    gif_scan<<<(B_*E_ + 127) / 128, 128>>>(buf2, s2h, E_);

    // out: logits = spikes2 @ outW + outb                 [4096 x 32000, K=1024]
    gemm_h<false><<<dim3(M_/PBM, V_/PBN), 512, SMEM_BYTES>>>(
        s2h, outWt, outb, nullptr, 0.f, out, M_, V_, E_);
}

// round 10
// speedup vs baseline: 1.6857x; 1.0002x over previous
#include <cuda_runtime.h>
#include <cuda_fp16.h>
#include <cstdint>
#include <cstddef>

#define DECAY 0.9f

#define B_ 2
#define S_ 2048
#define V_ 32000
#define E_ 1024
#define H_ 2048
#define M_ (B_*S_)   // 4096 rows

// Scratch (allocation-free rule: device globals)
__device__ float  g_buf1[(size_t)M_ * H_];    // 32 MB: cur1 (f32)
__device__ float  g_buf2[(size_t)M_ * E_];    // 16 MB: cur2 (f32)
__device__ __half g_s1h [(size_t)M_ * H_];    // 16 MB: spikes1 (fp16)
__device__ __half g_s2h [(size_t)M_ * E_];    //  8 MB: spikes2 (fp16)
__device__ __half g_embH[(size_t)M_ * E_];    //  8 MB: gathered embeddings (fp16)
__device__ __half g_encWt[(size_t)H_ * E_];   //  4 MB: enc_W^T  [H][E]
__device__ __half g_decWt[(size_t)E_ * H_];   //  4 MB: dec_W^T  [E][H]
__device__ __half g_outWt[(size_t)V_ * E_];   // 64 MB: out_W^T  [V][E]
__device__ int    g_ids_is64;

// ---------------------------------------------------------------------------
// helpers
// ---------------------------------------------------------------------------
__device__ __forceinline__ float fast_ex2(float x) {
    float y; asm("ex2.approx.f32 %0, %1;" : "=f"(y) : "f"(x)); return y;
}
__device__ __forceinline__ float fast_rcp(float x) {
    float y; asm("rcp.approx.f32 %0, %1;" : "=f"(y) : "f"(x)); return y;
}
__device__ __forceinline__ void mma16(float* c, const unsigned* a, const unsigned* b) {
    asm volatile(
        "mma.sync.aligned.m16n8k16.row.col.f32.f16.f16.f32 "
        "{%0,%1,%2,%3}, {%4,%5,%6,%7}, {%8,%9}, {%0,%1,%2,%3};\n"
        : "+f"(c[0]), "+f"(c[1]), "+f"(c[2]), "+f"(c[3])
        : "r"(a[0]), "r"(a[1]), "r"(a[2]), "r"(a[3]), "r"(b[0]), "r"(b[1]));
}
__device__ __forceinline__ void ldsm4(unsigned& r0, unsigned& r1, unsigned& r2,
                                      unsigned& r3, uint32_t a) {
    asm volatile("ldmatrix.sync.aligned.m8n8.x4.shared.b16 {%0,%1,%2,%3}, [%4];"
                 : "=r"(r0), "=r"(r1), "=r"(r2), "=r"(r3) : "r"(a));
}
__device__ __forceinline__ uint32_t smem_u32(const void* p) {
    uint32_t a;
    asm("{ .reg .u64 t; cvta.to.shared.u64 t, %1; cvt.u32.u64 %0, t; }" : "=r"(a) : "l"(p));
    return a;
}
__device__ __forceinline__ void cp16(uint32_t s, const void* g) {
    asm volatile("cp.async.cg.shared.global [%0], [%1], 16;" :: "r"(s), "l"(g) : "memory");
}
__device__ __forceinline__ void cp_commit() {
    asm volatile("cp.async.commit_group;" ::: "memory");
}
template<int N>
__device__ __forceinline__ void cp_wait() {
    asm volatile("cp.async.wait_group %0;" :: "n"(N) : "memory");
}

// ---------------------------------------------------------------------------
// dtype sniffer for input_ids (int32 vs int64)
// ---------------------------------------------------------------------------
__global__ void sniff_ids(const int* __restrict__ ids32) {
    if (threadIdx.x == 0 && blockIdx.x == 0) {
        int zeros = 0;
        for (int i = 1; i < 255; i += 2) zeros += (ids32[i] == 0);
        g_ids_is64 = (zeros > 64) ? 1 : 0;
    }
}

// ---------------------------------------------------------------------------
// weight transpose + fp32->fp16:  W[K][N] -> Wt[N][K]
// ---------------------------------------------------------------------------
__global__ void conv_transpose(const float* __restrict__ W, __half* __restrict__ Wt,
                               int K, int N)
{
    __shared__ float ts[64][65];
    const int k0 = blockIdx.y * 64, n0 = blockIdx.x * 64;
    const int t  = threadIdx.x;

    const int lk = t >> 4, ln = (t & 15) * 4;
    #pragma unroll
    for (int i = 0; i < 4; i++) {
        float4 v = *(const float4*)&W[(size_t)(k0 + lk + 16 * i) * N + n0 + ln];
        ts[lk + 16 * i][ln]     = v.x;
        ts[lk + 16 * i][ln + 1] = v.y;
        ts[lk + 16 * i][ln + 2] = v.z;
        ts[lk + 16 * i][ln + 3] = v.w;
    }
    __syncthreads();

    const int sn = t >> 2, sk = (t & 3) * 16;
    uint4 o[2];
    __half2* oh = (__half2*)o;
    #pragma unroll
    for (int j = 0; j < 8; j++)
        oh[j] = __floats2half2_rn(ts[sk + 2*j][sn], ts[sk + 2*j + 1][sn]);
    uint4* dst = (uint4*)&Wt[(size_t)(n0 + sn) * K + k0 + sk];
    dst[0] = o[0];
    dst[1] = o[1];
}

// ---------------------------------------------------------------------------
// embedding gather -> fp16
// ---------------------------------------------------------------------------
__global__ void gather_h(const float* __restrict__ emb, const void* __restrict__ idsv,
                         __half* __restrict__ dst)
{
    const int row = blockIdx.x;
    long long id = g_ids_is64 ? ((const long long*)idsv)[row]
                              : (long long)((const int*)idsv)[row];
    const float4* s = (const float4*)(emb + (size_t)id * E_);
    __half2* d = (__half2*)(dst + (size_t)row * E_);
    const int c = threadIdx.x;            // 256 threads, E/4 = 256 float4
    float4 v = s[c];
    d[2*c]   = __floats2half2_rn(v.x, v.y);
    d[2*c+1] = __floats2half2_rn(v.z, v.w);
}

// ---------------------------------------------------------------------------
// fp16 NT GEMM:  C[M,N](f32) = (A[M,K](h) @ Wt[N,K](h)^T + bias) * rowscale
// Block 128x256x32, 5-stage cp.async, 512 threads / 16 warps (2m x 8n),
// warp tile 64x32, mma.m16n8k16 with ldmatrix.x4.
// SMEM rows pitch 40 halfs (80B) => LDSM conflict-free.
// ---------------------------------------------------------------------------
#define PBM 128
#define PBN 256
#define PBK 32
#define STAGES 5
#define ROW_B 80                              // bytes per smem row (40 halfs)
#define A_BYTES (PBM * ROW_B)                 // 10240
#define B_BYTES (PBN * ROW_B)                 // 20480
#define STG_B (A_BYTES + B_BYTES)             // 30720
#define SMEM_BYTES (STAGES * STG_B)           // 153600

template<bool SCALE>
__global__ void __launch_bounds__(512, 1)
gemm_h(const __half* __restrict__ A, const __half* __restrict__ Wt,
       const float* __restrict__ bias, const float* __restrict__ gains,
       float strength, float* __restrict__ C, int M, int N, int K)
{
    extern __shared__ __align__(16) char sm[];
    const uint32_t sbase = smem_u32(sm);

    const int tid = threadIdx.x;
    const int bm0 = blockIdx.x * PBM;
    const int bn0 = blockIdx.y * PBN;

    // ---- copy mapping: 4 threads per row (16B chunks along K), 512 threads ----
    const int crow = tid >> 2;                // 0..127
    const int cchk = tid & 3;
    const __half* ag = A  + (size_t)(bm0 + crow) * K + cchk * 8;
    const __half* bg = Wt + (size_t)(bn0 + crow) * K + cchk * 8;
    const size_t rowStep = (size_t)128 * K;

    const int niter = K / PBK;

    auto issue = [&](int stage, int k0) {
        const uint32_t sa = sbase + stage * STG_B;
        cp16(sa + crow * ROW_B + cchk * 16, ag + k0);            // A: 128 rows
        const uint32_t sb = sa + A_BYTES;
        #pragma unroll
        for (int j = 0; j < 2; j++)                               // B: 256 rows
            cp16(sb + (crow + 128 * j) * ROW_B + cchk * 16,
                 bg + (size_t)j * rowStep + k0);
    };

    // ---- mma mapping: 16 warps 2m x 8n, warp tile 64x32 ----
    const int lane = tid & 31;
    const int wid  = tid >> 5;
    const int wm   = (wid & 1) * 64;
    const int wn   = (wid >> 1) * 32;
    const int ar   = lane >> 2;                // 0..7
    const int ac   = lane & 3;                 // 0..3

    // ldmatrix lane address offsets (within a stage)
    const int a_row16 = ((lane >> 3) & 1) * 8 + (lane & 7);
    const int a_koff  = (lane >> 4) * 8;              // halfs
    uint32_t aoff[4];
    #pragma unroll
    for (int mi = 0; mi < 4; mi++)
        aoff[mi] = (uint32_t)(wm + mi * 16 + a_row16) * ROW_B + a_koff * 2;
    const int b_rowsel = ((lane >> 4) & 1) * 8 + (lane & 7);
    const int b_koff   = ((lane >> 3) & 1) * 8;       // halfs
    uint32_t boff[2];
    #pragma unroll
    for (int p = 0; p < 2; p++)
        boff[p] = A_BYTES + (uint32_t)(wn + p * 16 + b_rowsel) * ROW_B + b_koff * 2;

    float acc[4][4][4];
    #pragma unroll
    for (int mi = 0; mi < 4; mi++)
        #pragma unroll
        for (int ni = 0; ni < 4; ni++)
            #pragma unroll
            for (int j = 0; j < 4; j++) acc[mi][ni][j] = 0.f;

    #pragma unroll
    for (int s = 0; s < STAGES - 1; s++) {
        if (s < niter) issue(s, s * PBK);
        cp_commit();
    }

    for (int kt = 0; kt < niter; kt++) {
        cp_wait<STAGES - 2>();
        __syncthreads();

        const int nk = kt + STAGES - 1;
        if (nk < niter) issue(nk % STAGES, nk * PBK);
        cp_commit();

        const uint32_t stb = sbase + (uint32_t)(kt % STAGES) * STG_B;

        #pragma unroll
        for (int ks = 0; ks < PBK; ks += 16) {
            const uint32_t kb = ks * 2;        // byte offset along K
            unsigned a[4][4], b[4][2];
            #pragma unroll
            for (int mi = 0; mi < 4; mi++)
                ldsm4(a[mi][0], a[mi][1], a[mi][2], a[mi][3], stb + aoff[mi] + kb);
            #pragma unroll
            for (int p = 0; p < 2; p++)
                ldsm4(b[2*p][0], b[2*p][1], b[2*p+1][0], b[2*p+1][1],
                      stb + boff[p] + kb);
            #pragma unroll
            for (int mi = 0; mi < 4; mi++)
                #pragma unroll
                for (int ni = 0; ni < 4; ni++)
                    mma16(acc[mi][ni], a[mi], b[ni]);
        }
    }

    // ---- epilogue: bias + optional row scale ----
    #pragma unroll
    for (int mi = 0; mi < 4; mi++) {
        const int r0 = bm0 + wm + mi * 16 + ar;
        const int r1 = r0 + 8;
        float s0 = 1.f, s1 = 1.f;
        if (SCALE) {
            s0 = 1.f + strength * (gains[r0] - 1.f);
            s1 = 1.f + strength * (gains[r1] - 1.f);
        }
        #pragma unroll
        for (int ni = 0; ni < 4; ni++) {
            const int col = bn0 + wn + ni * 8 + ac * 2;
            const float b0 = bias[col], b1 = bias[col + 1];
            float2 o0, o1;
            o0.x = (acc[mi][ni][0] + b0) * s0;
            o0.y = (acc[mi][ni][1] + b1) * s0;
            o1.x = (acc[mi][ni][2] + b0) * s1;
            o1.y = (acc[mi][ni][3] + b1) * s1;
            *(float2*)&C[(size_t)r0 * N + col] = o0;
            *(float2*)&C[(size_t)r1 * N + col] = o1;
        }
    }
}

// ---------------------------------------------------------------------------
// GIF scan: cur (f32) -> spikes (fp16); sequential over S per channel.
// 16-wide groups, double-buffered prefetch: loads of group i+1 overlap the
// 16-step serial compute of group i (only 2B/4K channels exist, so ILP is
// the only latency lever).
// ---------------------------------------------------------------------------
__global__ void gif_scan(const float* __restrict__ cur, __half* __restrict__ spk, int D)
{
    const int t = blockIdx.x * blockDim.x + threadIdx.x;
    if (t >= B_ * D) return;
    const int b = t / D, d = t % D;
    const float* p = cur + (size_t)b * S_ * D + d;
    __half* q = spk + (size_t)b * S_ * D + d;

    const float KX = 4.0f * 1.4426950408889634f;  // 4*log2(e)
    float c[2][16];
    #pragma unroll
    for (int i = 0; i < 16; i++) c[0][i] = p[(size_t)i * D];

    float v = 0.f;
    #pragma unroll 1
    for (int s0 = 0; s0 < S_; s0 += 16) {
        const int buf = (s0 >> 4) & 1;
        if (s0 + 16 < S_) {
            #pragma unroll
            for (int i = 0; i < 16; i++)
                c[buf ^ 1][i] = p[(size_t)(s0 + 16 + i) * D];
        }
        #pragma unroll
        for (int i = 0; i < 16; i++) {
            v = fmaf(DECAY, v, c[buf][i]);
            const float e  = fast_ex2(fmaf(-KX, v, KX));   // exp(-4(v-1))
            const float sp = fast_rcp(1.0f + e);
            q[(size_t)(s0 + i) * D] = __float2half_rn(sp);
            v -= sp;
        }
    }
}

// ---------------------------------------------------------------------------
// launch
// ---------------------------------------------------------------------------
extern "C" void kernel_launch(void* const* d_in, const int* in_sizes, int n_in,
                              void* d_out, int out_size)
{
    const void*  ids   = d_in[0];
    const float* gains = (const float*)d_in[1];
    const float* emb   = (const float*)d_in[2];
    const float* encW  = (const float*)d_in[3];
    const float* encb  = (const float*)d_in[4];
    const float* decW  = (const float*)d_in[5];
    const float* decb  = (const float*)d_in[6];
    const float* outW  = (const float*)d_in[7];
    const float* outb  = (const float*)d_in[8];
    float* out = (float*)d_out;

    float  *buf1, *buf2;
    __half *s1h, *s2h, *embH, *encWt, *decWt, *outWt;
    cudaGetSymbolAddress((void**)&buf1,  g_buf1);
    cudaGetSymbolAddress((void**)&buf2,  g_buf2);
    cudaGetSymbolAddress((void**)&s1h,   g_s1h);
    cudaGetSymbolAddress((void**)&s2h,   g_s2h);
    cudaGetSymbolAddress((void**)&embH,  g_embH);
    cudaGetSymbolAddress((void**)&encWt, g_encWt);
    cudaGetSymbolAddress((void**)&decWt, g_decWt);
    cudaGetSymbolAddress((void**)&outWt, g_outWt);

    cudaFuncSetAttribute(gemm_h<true>,  cudaFuncAttributeMaxDynamicSharedMemorySize, SMEM_BYTES);
    cudaFuncSetAttribute(gemm_h<false>, cudaFuncAttributeMaxDynamicSharedMemorySize, SMEM_BYTES);

    sniff_ids<<<1, 32>>>((const int*)ids);

    // fp16 operand prep
    gather_h<<<M_, 256>>>(emb, ids, embH);
    conv_transpose<<<dim3(H_/64, E_/64), 256>>>(encW, encWt, E_, H_);
    conv_transpose<<<dim3(E_/64, H_/64), 256>>>(decW, decWt, H_, E_);
    conv_transpose<<<dim3(V_/64, E_/64), 256>>>(outW, outWt, E_, V_);

    // enc: cur1 = (embH @ encW + encb) * (1+0.3*(g-1))    [4096 x 2048, K=1024]
    gemm_h<true><<<dim3(M_/PBM, H_/PBN), 512, SMEM_BYTES>>>(
        embH, encWt, encb, gains, 0.3f, buf1, M_, H_, E_);
    gif_scan<<<(B_*H_ + 127) / 128, 128>>>(buf1, s1h, H_);

    // dec: cur2 = (spikes1 @ decW + decb) * (1+0.2*(g-1)) [4096 x 1024, K=2048]
    gemm_h<true><<<dim3(M_/PBM, E_/PBN), 512, SMEM_BYTES>>>(
        s1h, decWt, decb, gains, 0.2f, buf2, M_, E_, H_);
    gif_scan<<<(B_*E_ + 127) / 128, 128>>>(buf2, s2h, E_);

    // out: logits = spikes2 @ outW + outb                 [4096 x 32000, K=1024]
    gemm_h<false><<<dim3(M_/PBM, V_/PBN), 512, SMEM_BYTES>>>(
        s2h, outWt, outb, nullptr, 0.f, out, M_, V_, E_);
}